// round 9
// baseline (speedup 1.0000x reference)
#include <cuda_runtime.h>
#include <cuda_fp16.h>
#include <math_constants.h>
#include <cstdint>

#define NB 32
#define NPROP 256
#define NCLS 19
#define NPTS 4096
#define NBQ 64
#define NCK 64
#define CDIM 256
#define QHD 768
#define VQn 8
#define MROWS (NB*NBQ)                 // 2048
#define OUTROWS 1024
#define FEAT_ELEMS (NB*OUTROWS*QHD)    // 25165824

// ================= device scratch =================
__device__ float g_mn[NB*NPROP*3];
__device__ float g_mx[NB*NPROP*3];
__device__ float g_vol[NB*NPROP];
__device__ float g_pmask[NB*NPROP];
__device__ int   g_match[MROWS];
__device__ unsigned long long g_nnpack[MROWS];

__device__ __half g_bxA[MROWS*CDIM];        // [2048,256]
__device__ __half g_ckA[MROWS*2*CDIM];      // [2048,512]
__device__ __half g_w1b[QHD*CDIM];          // [768,256]  (N,K)
__device__ __half g_w1c[QHD*2*CDIM];        // [768,512]
__device__ __half g_w2b[VQn*QHD*QHD];       // [6144,768]
__device__ __half g_w2c[VQn*QHD*QHD];       // [6144,768]
__device__ __half g_h1[MROWS*QHD];          // box hidden fp16
__device__ __half g_h2[MROWS*QHD];          // click hidden fp16

// ================= helpers =================
__device__ __forceinline__ uint32_t smem_u32(const void* p) {
    uint32_t a;
    asm("{ .reg .u64 t; cvta.to.shared.u64 t, %1; cvt.u32.u64 %0, t; }" : "=r"(a) : "l"(p));
    return a;
}
__device__ __forceinline__ void cp16(uint32_t dst, const void* src) {
    asm volatile("cp.async.cg.shared.global [%0], [%1], 16;" :: "r"(dst), "l"(src));
}
#define CP_COMMIT() asm volatile("cp.async.commit_group;" ::: "memory")
#define CP_WAIT1()  asm volatile("cp.async.wait_group 1;" ::: "memory")

__device__ __forceinline__ void ldsm_x4(uint32_t* r, uint32_t addr) {
    asm volatile("ldmatrix.sync.aligned.m8n8.x4.shared.b16 {%0,%1,%2,%3}, [%4];"
        : "=r"(r[0]), "=r"(r[1]), "=r"(r[2]), "=r"(r[3]) : "r"(addr));
}
__device__ __forceinline__ void ldsm_x2(uint32_t* r, uint32_t addr) {
    asm volatile("ldmatrix.sync.aligned.m8n8.x2.shared.b16 {%0,%1}, [%2];"
        : "=r"(r[0]), "=r"(r[1]) : "r"(addr));
}
__device__ __forceinline__ void mma16816(float* d, const uint32_t* a, const uint32_t* b) {
    asm volatile(
        "mma.sync.aligned.m16n8k16.row.col.f32.f16.f16.f32 "
        "{%0,%1,%2,%3}, {%4,%5,%6,%7}, {%8,%9}, {%0,%1,%2,%3};"
        : "+f"(d[0]), "+f"(d[1]), "+f"(d[2]), "+f"(d[3])
        : "r"(a[0]), "r"(a[1]), "r"(a[2]), "r"(a[3]), "r"(b[0]), "r"(b[1]));
}

// ================= prep kernels =================
__global__ void prop_prep(const float* __restrict__ logits, const float* __restrict__ corners) {
    int p = blockIdx.x * blockDim.x + threadIdx.x;
    if (p >= NB*NPROP) return;
    const float* l = logits + (size_t)p * NCLS;
    float best = l[0]; int bi = 0;
    #pragma unroll
    for (int k = 1; k < NCLS; k++) { float v = l[k]; if (v > best) { best = v; bi = k; } }
    g_pmask[p] = (bi != NCLS - 1) ? 1.f : 0.f;
    const float* cr = corners + (size_t)p * 24;
    float mn0 = cr[0], mn1 = cr[1], mn2 = cr[2];
    float mx0 = cr[0], mx1 = cr[1], mx2 = cr[2];
    #pragma unroll
    for (int c = 1; c < 8; c++) {
        float x = cr[c*3+0], y = cr[c*3+1], z = cr[c*3+2];
        mn0 = fminf(mn0, x); mx0 = fmaxf(mx0, x);
        mn1 = fminf(mn1, y); mx1 = fmaxf(mx1, y);
        mn2 = fminf(mn2, z); mx2 = fmaxf(mx2, z);
    }
    g_mn[p*3+0] = mn0; g_mn[p*3+1] = mn1; g_mn[p*3+2] = mn2;
    g_mx[p*3+0] = mx0; g_mx[p*3+1] = mx1; g_mx[p*3+2] = mx2;
    g_vol[p] = (mx0-mn0)*(mx1-mn1)*(mx2-mn2);
}

__global__ void nn_init() {
    int i = blockIdx.x * blockDim.x + threadIdx.x;
    if (i < MROWS) g_nnpack[i] = ~0ull;
}

__global__ void box_match(const float* __restrict__ box_query) {
    __shared__ float s_mn[NPROP*3], s_mx[NPROP*3], s_vol[NPROP], s_msk[NPROP];
    int b = blockIdx.x, t = threadIdx.x;
    if (t < NPROP) {
        int p = b*NPROP + t;
        s_mn[t*3+0] = g_mn[p*3+0]; s_mn[t*3+1] = g_mn[p*3+1]; s_mn[t*3+2] = g_mn[p*3+2];
        s_mx[t*3+0] = g_mx[p*3+0]; s_mx[t*3+1] = g_mx[p*3+1]; s_mx[t*3+2] = g_mx[p*3+2];
        s_vol[t] = g_vol[p]; s_msk[t] = g_pmask[p];
    }
    __syncthreads();
    if (t < NBQ) {
        const float* cq = box_query + ((size_t)b*NBQ + t) * 24;
        float mn0 = cq[0], mn1 = cq[1], mn2 = cq[2];
        float mx0 = cq[0], mx1 = cq[1], mx2 = cq[2];
        #pragma unroll
        for (int c = 1; c < 8; c++) {
            float x = cq[c*3+0], y = cq[c*3+1], z = cq[c*3+2];
            mn0 = fminf(mn0, x); mx0 = fmaxf(mx0, x);
            mn1 = fminf(mn1, y); mx1 = fmaxf(mx1, y);
            mn2 = fminf(mn2, z); mx2 = fmaxf(mx2, z);
        }
        float volq = (mx0-mn0)*(mx1-mn1)*(mx2-mn2);
        float best = -1.f; int bi = 0;
        for (int p = 0; p < NPROP; p++) {
            float ix = fmaxf(fminf(mx0, s_mx[p*3+0]) - fmaxf(mn0, s_mn[p*3+0]), 0.f);
            float iy = fmaxf(fminf(mx1, s_mx[p*3+1]) - fmaxf(mn1, s_mn[p*3+1]), 0.f);
            float iz = fmaxf(fminf(mx2, s_mx[p*3+2]) - fmaxf(mn2, s_mn[p*3+2]), 0.f);
            float inter = ix*iy*iz;
            float iou = inter / (volq + s_vol[p] - inter + 1e-8f) * s_msk[p];
            if (iou > best) { best = iou; bi = p; }
        }
        g_match[b*NBQ + t] = bi;
    }
}

// warp-per-row gather: 8 warps/block, 256 rows total per 32-block grid
__global__ void gather_box(const float* __restrict__ prop_features) {
    int warp = (blockIdx.x * blockDim.x + threadIdx.x) >> 5;
    int lane = threadIdx.x & 31;
    if (warp >= MROWS) return;
    int b = warp >> 6;
    int m = g_match[warp];
    const float4* src = (const float4*)(prop_features + ((size_t)b*NPROP + m) * CDIM);
    __half* dst = g_bxA + (size_t)warp * CDIM;
    #pragma unroll
    for (int i = 0; i < 2; i++) {
        float4 v = src[lane + i*32];
        int o = (lane + i*32) * 4;
        dst[o+0] = __float2half_rn(v.x);
        dst[o+1] = __float2half_rn(v.y);
        dst[o+2] = __float2half_rn(v.z);
        dst[o+3] = __float2half_rn(v.w);
    }
}

#define NN_PTS 512
__global__ void click_nn(const float* __restrict__ enc_xyz, const float* __restrict__ click_query) {
    __shared__ float s_xyz[NN_PTS*3];
    int b = blockIdx.x, ck = blockIdx.y, t = threadIdx.x;
    const float* src = enc_xyz + ((size_t)b*NPTS + ck*NN_PTS) * 3;
    for (int i = t; i < NN_PTS*3; i += 256) s_xyz[i] = src[i];
    __syncthreads();
    int warp = t >> 5, lane = t & 31;
    for (int q = warp; q < NCK; q += 8) {
        const float* cq = click_query + ((size_t)b*NCK + q) * 3;
        float cx = cq[0], cy = cq[1], cz = cq[2];
        float best = CUDART_INF_F; int bi = 0;
        for (int p = lane; p < NN_PTS; p += 32) {
            float dx = cx - s_xyz[p*3+0];
            float dy = cy - s_xyz[p*3+1];
            float dz = cz - s_xyz[p*3+2];
            float d = dx*dx + dy*dy + dz*dz;
            if (d < best) { best = d; bi = p; }
        }
        #pragma unroll
        for (int off = 16; off; off >>= 1) {
            float ob = __shfl_xor_sync(0xffffffffu, best, off);
            int   oi = __shfl_xor_sync(0xffffffffu, bi, off);
            if (ob < best || (ob == best && oi < bi)) { best = ob; bi = oi; }
        }
        if (lane == 0) {
            unsigned long long key = ((unsigned long long)__float_as_uint(best) << 32)
                                   | (unsigned)(ck*NN_PTS + bi);
            atomicMin(&g_nnpack[b*NCK + q], key);
        }
    }
}

__global__ void click_build(const float* __restrict__ enc_features,
                            const float* __restrict__ click_query,
                            const float* __restrict__ pc_min,
                            const float* __restrict__ pc_max,
                            const float* __restrict__ gauss) {
    int r = blockIdx.x, t = threadIdx.x;  // 128 threads
    int b = r >> 6;
    int nn = (int)(g_nnpack[r] & 0xffffffffull);
    const float2* src = (const float2*)(enc_features + ((size_t)b*NPTS + nn) * CDIM);
    float2 v = src[t];
    int o = r*2*CDIM + 2*t;
    g_ckA[o+0] = __float2half_rn(v.x);
    g_ckA[o+1] = __float2half_rn(v.y);
    const float* cq = click_query + (size_t)r * 3;
    float pr = 0.f;
    #pragma unroll
    for (int d = 0; d < 3; d++) {
        float x01 = (cq[d] - pc_min[b*3+d]) / (pc_max[b*3+d] - pc_min[b*3+d]);
        pr += x01 * 6.283185307179586f * gauss[d*(CDIM/2) + t];
    }
    g_ckA[r*2*CDIM + CDIM + t]       = __float2half_rn(sinf(pr));
    g_ckA[r*2*CDIM + CDIM + 128 + t] = __float2half_rn(cosf(pr));
}

// transpose + fp16 convert: src [K,N] f32 -> dst [N,K] fp16
__global__ void tconv(const float* __restrict__ src, __half* __restrict__ dh, int K, int N) {
    __shared__ float tile[32][33];
    int n0 = blockIdx.x*32, k0 = blockIdx.y*32;
    int tx = threadIdx.x, ty = threadIdx.y;
    #pragma unroll
    for (int j = 0; j < 4; j++)
        tile[ty + 8*j][tx] = src[(size_t)(k0 + ty + 8*j) * N + n0 + tx];
    __syncthreads();
    #pragma unroll
    for (int j = 0; j < 4; j++)
        dh[(size_t)(n0 + ty + 8*j) * K + k0 + tx] = __float2half_rn(tile[tx][ty + 8*j]);
}

// ================= HMMA GEMM bodies =================
#define ROWB 80
#define NSTAGE 3

// ---- layer 1: 128x128 CTA tile, warp tile 64x32 (2M x 4N warps) ----
#define T1_A (128*ROWB)              // 10240
#define T1_STAGE (2*T1_A)            // A + B
__device__ __forceinline__ void gemm_body128(
        const __half* __restrict__ A, const __half* __restrict__ B,
        int K, int m0, int n0, uint32_t base, int t, float acc[4][4][4]) {
    const int lid = t & 31;
    const int mwarp = (t >> 5) & 1, nwarp = t >> 6;
    const int S = K >> 5;

    auto load_slab = [&](int s) {
        uint32_t sb = base + (s % NSTAGE) * T1_STAGE;
        size_t kof = (size_t)s * 32;
        #pragma unroll
        for (int i = 0; i < 4; i++) {
            int c = i * 256 + t;
            int tile = c >> 9, local = c & 511;
            int row = local >> 2, chk = local & 3;
            uint32_t dst = sb + tile * T1_A + row * ROWB + chk * 16;
            const __half* srcp = (tile == 0)
                ? A + (size_t)(m0 + row) * K + kof + chk * 8
                : B + (size_t)(n0 + row) * K + kof + chk * 8;
            cp16(dst, srcp);
        }
    };
    auto compute_stage = [&](int s) {
        uint32_t sb = base + (s % NSTAGE) * T1_STAGE;
        uint32_t aP = sb, bP = sb + T1_A;
        #pragma unroll
        for (int ks = 0; ks < 32; ks += 16) {
            uint32_t ah[4][4], bh[4][2];
            uint32_t aoff = (uint32_t)((mwarp*64 + (lid & 15)) * ROWB
                                       + (ks + ((lid >> 4) << 3)) * 2);
            #pragma unroll
            for (int mi = 0; mi < 4; mi++)
                ldsm_x4(ah[mi], aP + aoff + mi*16*ROWB);
            uint32_t boff = (uint32_t)((nwarp*32 + (lid & 7)) * ROWB
                                       + (ks + (((lid >> 3) & 1) << 3)) * 2);
            #pragma unroll
            for (int ni = 0; ni < 4; ni++)
                ldsm_x2(bh[ni], bP + boff + ni*8*ROWB);
            #pragma unroll
            for (int mi = 0; mi < 4; mi++)
                #pragma unroll
                for (int ni = 0; ni < 4; ni++)
                    mma16816(acc[mi][ni], ah[mi], bh[ni]);
        }
    };

    load_slab(0); CP_COMMIT();
    if (S > 1) load_slab(1);
    CP_COMMIT();
    for (int s = 0; s < S; s++) {
        CP_WAIT1();
        __syncthreads();
        if (s + 2 < S) load_slab(s + 2);
        CP_COMMIT();
        compute_stage(s);
    }
}

// ---- layer 2: 256x128 CTA tile, warp tile 64x64 (4M x 2N warps) ----
#define T2_A (256*ROWB)              // 20480
#define T2_B (128*ROWB)              // 10240
#define T2_STAGE (T2_A + T2_B)       // 30720
__device__ __forceinline__ void gemm_body256(
        const __half* __restrict__ A, const __half* __restrict__ B,
        int K, int m0, int n0, uint32_t base, int t, float acc[4][8][4]) {
    const int lid = t & 31;
    const int mwarp = t >> 6;            // 0..3 (wid>>1? no: 4 m-warps = wid&3?) see below
    const int nwarp = (t >> 5) & 1;      // 0..1
    const int S = K >> 5;

    auto load_slab = [&](int s) {
        uint32_t sb = base + (s % NSTAGE) * T2_STAGE;
        size_t kof = (size_t)s * 32;
        #pragma unroll
        for (int i = 0; i < 4; i++) {                  // A: 256 rows x 4 chunks
            int c = i * 256 + t;
            int row = c >> 2, chk = c & 3;
            cp16(sb + row * ROWB + chk * 16,
                 A + (size_t)(m0 + row) * K + kof + chk * 8);
        }
        #pragma unroll
        for (int i = 0; i < 2; i++) {                  // B: 128 rows x 4 chunks
            int c = i * 256 + t;
            int row = c >> 2, chk = c & 3;
            cp16(sb + T2_A + row * ROWB + chk * 16,
                 B + (size_t)(n0 + row) * K + kof + chk * 8);
        }
    };
    auto compute_stage = [&](int s) {
        uint32_t sb = base + (s % NSTAGE) * T2_STAGE;
        uint32_t aP = sb, bP = sb + T2_A;
        #pragma unroll
        for (int ks = 0; ks < 32; ks += 16) {
            uint32_t ah[4][4], bh[8][2];
            uint32_t aoff = (uint32_t)((mwarp*64 + (lid & 15)) * ROWB
                                       + (ks + ((lid >> 4) << 3)) * 2);
            #pragma unroll
            for (int mi = 0; mi < 4; mi++)
                ldsm_x4(ah[mi], aP + aoff + mi*16*ROWB);
            uint32_t boff = (uint32_t)((nwarp*64 + (lid & 7)) * ROWB
                                       + (ks + (((lid >> 3) & 1) << 3)) * 2);
            #pragma unroll
            for (int ni = 0; ni < 8; ni++)
                ldsm_x2(bh[ni], bP + boff + ni*8*ROWB);
            #pragma unroll
            for (int mi = 0; mi < 4; mi++)
                #pragma unroll
                for (int ni = 0; ni < 8; ni++)
                    mma16816(acc[mi][ni], ah[mi], bh[ni]);
        }
    };

    load_slab(0); CP_COMMIT();
    if (S > 1) load_slab(1);
    CP_COMMIT();
    for (int s = 0; s < S; s++) {
        CP_WAIT1();
        __syncthreads();
        if (s + 2 < S) load_slab(s + 2);
        CP_COMMIT();
        compute_stage(s);
    }
}

// layer 1 (both branches via blockIdx.z): relu(D+bias) -> fp16 hidden
__global__ __launch_bounds__(256, 2) void tgemm_l1(
        const __half* A0, const __half* B0, const float* b0, int K0, __half* H0,
        const __half* A1, const __half* B1, const float* b1, int K1, __half* H1) {
    extern __shared__ __align__(16) char smem_raw[];
    const uint32_t base = smem_u32(smem_raw);
    float* s_bias = (float*)(smem_raw + NSTAGE * T1_STAGE);
    int z = blockIdx.z, t = threadIdx.x;
    const __half* A = z ? A1 : A0;
    const __half* B = z ? B1 : B0;
    const float* bias = z ? b1 : b0;
    int K = z ? K1 : K0;
    __half* H = z ? H1 : H0;
    int m0 = blockIdx.y * 128, n0 = blockIdx.x * 128;
    if (t < 128) s_bias[t] = bias[n0 + t];

    float acc[4][4][4];
    #pragma unroll
    for (int mi = 0; mi < 4; mi++)
        #pragma unroll
        for (int ni = 0; ni < 4; ni++)
            #pragma unroll
            for (int r = 0; r < 4; r++) acc[mi][ni][r] = 0.f;

    gemm_body128(A, B, K, m0, n0, base, t, acc);

    const int lid = t & 31;
    const int mb = m0 + ((t >> 5) & 1) * 64;
    const int nb = n0 + (t >> 6) * 32;
    #pragma unroll
    for (int mi = 0; mi < 4; mi++) {
        int r0 = mb + mi*16 + (lid >> 2);
        #pragma unroll
        for (int ni = 0; ni < 4; ni++) {
            int n = nb + ni*8 + (lid & 3)*2;
            float v00 = fmaxf(acc[mi][ni][0] + s_bias[n   - n0], 0.f);
            float v01 = fmaxf(acc[mi][ni][1] + s_bias[n+1 - n0], 0.f);
            float v10 = fmaxf(acc[mi][ni][2] + s_bias[n   - n0], 0.f);
            float v11 = fmaxf(acc[mi][ni][3] + s_bias[n+1 - n0], 0.f);
            size_t o0 = (size_t)r0 * QHD + n;
            size_t o1 = (size_t)(r0 + 8) * QHD + n;
            H[o0]   = __float2half_rn(v00);
            H[o0+1] = __float2half_rn(v01);
            H[o1]   = __float2half_rn(v10);
            H[o1+1] = __float2half_rn(v11);
        }
    }
}

// layer 2 (both branches via blockIdx.z): D+bias -> out remapped (b,q,v,h)
__global__ __launch_bounds__(256, 1) void tgemm_l2(
        const __half* A0, const __half* B0, const float* b0,
        const __half* A1, const __half* B1, const float* b1,
        float* __restrict__ outf) {
    extern __shared__ __align__(16) char smem_raw[];
    const uint32_t base = smem_u32(smem_raw);
    float* s_bias = (float*)(smem_raw + NSTAGE * T2_STAGE);
    int z = blockIdx.z, t = threadIdx.x;
    const __half* A = z ? A1 : A0;
    const __half* B = z ? B1 : B0;
    const float* bias = z ? b1 : b0;
    int m0 = blockIdx.y * 256, n0 = blockIdx.x * 128;
    if (t < 128) s_bias[t] = bias[n0 + t];

    float acc[4][8][4];
    #pragma unroll
    for (int mi = 0; mi < 4; mi++)
        #pragma unroll
        for (int ni = 0; ni < 8; ni++)
            #pragma unroll
            for (int r = 0; r < 4; r++) acc[mi][ni][r] = 0.f;

    gemm_body256(A, B, QHD, m0, n0, base, t, acc);

    const int lid = t & 31;
    const int mb = m0 + (t >> 6) * 64;          // mwarp = t>>6
    const int nb = n0 + ((t >> 5) & 1) * 64;    // nwarp
    const int boff = z ? (NBQ * VQn) : 0;
    #pragma unroll
    for (int mi = 0; mi < 4; mi++) {
        int r0 = mb + mi*16 + (lid >> 2);
        #pragma unroll
        for (int ni = 0; ni < 8; ni++) {
            int n = nb + ni*8 + (lid & 3)*2;
            float v00 = acc[mi][ni][0] + s_bias[n   - n0];
            float v01 = acc[mi][ni][1] + s_bias[n+1 - n0];
            float v10 = acc[mi][ni][2] + s_bias[n   - n0];
            float v11 = acc[mi][ni][3] + s_bias[n+1 - n0];
            int vq = n / QHD, h = n - vq * QHD;
            int b0i = r0 >> 6, q0 = r0 & 63;
            int r1 = r0 + 8;
            int b1i = r1 >> 6, q1 = r1 & 63;
            size_t o0 = ((size_t)(b0i*OUTROWS + boff + q0*VQn + vq)) * QHD + h;
            size_t o1 = ((size_t)(b1i*OUTROWS + boff + q1*VQn + vq)) * QHD + h;
            outf[o0]   = v00; outf[o0+1] = v01;
            outf[o1]   = v10; outf[o1+1] = v11;
        }
    }
}

__global__ void write_mask(const float* __restrict__ box_qmask,
                           const float* __restrict__ click_qmask,
                           float* __restrict__ out_mask) {
    int i = blockIdx.x * blockDim.x + threadIdx.x;
    if (i >= NB * OUTROWS) return;
    int b = i >> 10, r = i & 1023;
    float v = (r < NBQ*VQn) ? box_qmask[b*NBQ + (r >> 3)]
                            : click_qmask[b*NCK + ((r - NBQ*VQn) >> 3)];
    out_mask[i] = v;
}

// ================= host =================
extern "C" void kernel_launch(void* const* d_in, const int* in_sizes, int n_in,
                              void* d_out, int out_size) {
    const float* sem     = (const float*)d_in[0];
    const float* propf   = (const float*)d_in[1];
    const float* boxc    = (const float*)d_in[2];
    const float* encxyz  = (const float*)d_in[3];
    const float* encf    = (const float*)d_in[4];
    const float* pcmin   = (const float*)d_in[5];
    const float* pcmax   = (const float*)d_in[6];
    const float* boxq    = (const float*)d_in[7];
    const float* boxqm   = (const float*)d_in[8];
    const float* clickq  = (const float*)d_in[9];
    const float* clickqm = (const float*)d_in[10];
    const float* gauss   = (const float*)d_in[11];
    const float* bw1     = (const float*)d_in[12];
    const float* bb1     = (const float*)d_in[13];
    const float* bw2     = (const float*)d_in[14];
    const float* bb2     = (const float*)d_in[15];
    const float* cw1     = (const float*)d_in[16];
    const float* cb1     = (const float*)d_in[17];
    const float* cw2     = (const float*)d_in[18];
    const float* cb2     = (const float*)d_in[19];
    float* out = (float*)d_out;

    void *bxA, *ckA, *w1b, *w1c, *w2b, *w2c, *h1, *h2;
    cudaGetSymbolAddress(&bxA, g_bxA); cudaGetSymbolAddress(&ckA, g_ckA);
    cudaGetSymbolAddress(&w1b, g_w1b); cudaGetSymbolAddress(&w1c, g_w1c);
    cudaGetSymbolAddress(&w2b, g_w2b); cudaGetSymbolAddress(&w2c, g_w2c);
    cudaGetSymbolAddress(&h1,  g_h1);  cudaGetSymbolAddress(&h2,  g_h2);

    const int smem_l1 = NSTAGE * T1_STAGE + 512;   // 61952
    const int smem_l2 = NSTAGE * T2_STAGE + 512;   // 92672
    cudaFuncSetAttribute(tgemm_l1, cudaFuncAttributeMaxDynamicSharedMemorySize, smem_l1);
    cudaFuncSetAttribute(tgemm_l2, cudaFuncAttributeMaxDynamicSharedMemorySize, smem_l2);

    prop_prep<<<(NB*NPROP + 127)/128, 128>>>(sem, boxc);
    nn_init<<<(MROWS + 255)/256, 256>>>();
    box_match<<<NB, 256>>>(boxq);
    gather_box<<<MROWS/8, 256>>>(propf);
    click_nn<<<dim3(NB, NPTS/NN_PTS), 256>>>(encxyz, clickq);
    click_build<<<MROWS, 128>>>(encf, clickq, pcmin, pcmax, gauss);

    {
        dim3 blk(32, 8);
        tconv<<<dim3(QHD/32, CDIM/32),    blk>>>(bw1, (__half*)w1b, CDIM,   QHD);
        tconv<<<dim3(QHD/32, 2*CDIM/32),  blk>>>(cw1, (__half*)w1c, 2*CDIM, QHD);
        tconv<<<dim3(VQn*QHD/32, QHD/32), blk>>>(bw2, (__half*)w2b, QHD, VQn*QHD);
        tconv<<<dim3(VQn*QHD/32, QHD/32), blk>>>(cw2, (__half*)w2c, QHD, VQn*QHD);
    }

    // layer 1: both branches in one launch (z=2), M=2048, N=768
    tgemm_l1<<<dim3(QHD/128, MROWS/128, 2), 256, smem_l1>>>(
        (__half*)bxA, (__half*)w1b, bb1, CDIM,   (__half*)h1,
        (__half*)ckA, (__half*)w1c, cb1, 2*CDIM, (__half*)h2);

    // layer 2: both branches in one launch (z=2), M=2048 (256/CTA), N=6144
    tgemm_l2<<<dim3(VQn*QHD/128, MROWS/256, 2), 256, smem_l2>>>(
        (__half*)h1, (__half*)w2b, bb2,
        (__half*)h2, (__half*)w2c, cb2, out);

    write_mask<<<(NB*OUTROWS + 255)/256, 256>>>(boxqm, clickqm, out + FEAT_ELEMS);
}

// round 11
// speedup vs baseline: 1.1172x; 1.1172x over previous
#include <cuda_runtime.h>
#include <cuda_fp16.h>
#include <math_constants.h>
#include <cstdint>

#define NB 32
#define NPROP 256
#define NCLS 19
#define NPTS 4096
#define NBQ 64
#define NCK 64
#define CDIM 256
#define QHD 768
#define VQn 8
#define MROWS (NB*NBQ)                 // 2048
#define OUTROWS 1024
#define FEAT_ELEMS (NB*OUTROWS*QHD)    // 25165824

// ================= device scratch =================
__device__ float g_mn[NB*NPROP*3];
__device__ float g_mx[NB*NPROP*3];
__device__ float g_vol[NB*NPROP];
__device__ float g_pmask[NB*NPROP];
__device__ int   g_match[MROWS];
__device__ unsigned long long g_nnpack[MROWS];

__device__ __half g_bxA[MROWS*CDIM];        // [2048,256]
__device__ __half g_ckA[MROWS*2*CDIM];      // [2048,512]
__device__ __half g_w1b[QHD*CDIM];          // [768,256]  (N,K)
__device__ __half g_w1c[QHD*2*CDIM];        // [768,512]
__device__ __half g_w2b[VQn*QHD*QHD];       // [6144,768]
__device__ __half g_w2c[VQn*QHD*QHD];       // [6144,768]
__device__ __half g_h1[MROWS*QHD];          // box hidden fp16
__device__ __half g_h2[MROWS*QHD];          // click hidden fp16

// ================= helpers =================
__device__ __forceinline__ uint32_t smem_u32(const void* p) {
    uint32_t a;
    asm("{ .reg .u64 t; cvta.to.shared.u64 t, %1; cvt.u32.u64 %0, t; }" : "=r"(a) : "l"(p));
    return a;
}
__device__ __forceinline__ void cp16(uint32_t dst, const void* src) {
    asm volatile("cp.async.cg.shared.global [%0], [%1], 16;" :: "r"(dst), "l"(src));
}
#define CP_COMMIT() asm volatile("cp.async.commit_group;" ::: "memory")
#define CP_WAIT1()  asm volatile("cp.async.wait_group 1;" ::: "memory")

__device__ __forceinline__ void ldsm_x4(uint32_t* r, uint32_t addr) {
    asm volatile("ldmatrix.sync.aligned.m8n8.x4.shared.b16 {%0,%1,%2,%3}, [%4];"
        : "=r"(r[0]), "=r"(r[1]), "=r"(r[2]), "=r"(r[3]) : "r"(addr));
}
__device__ __forceinline__ void ldsm_x2(uint32_t* r, uint32_t addr) {
    asm volatile("ldmatrix.sync.aligned.m8n8.x2.shared.b16 {%0,%1}, [%2];"
        : "=r"(r[0]), "=r"(r[1]) : "r"(addr));
}
__device__ __forceinline__ void mma16816(float* d, const uint32_t* a, const uint32_t* b) {
    asm volatile(
        "mma.sync.aligned.m16n8k16.row.col.f32.f16.f16.f32 "
        "{%0,%1,%2,%3}, {%4,%5,%6,%7}, {%8,%9}, {%0,%1,%2,%3};"
        : "+f"(d[0]), "+f"(d[1]), "+f"(d[2]), "+f"(d[3])
        : "r"(a[0]), "r"(a[1]), "r"(a[2]), "r"(a[3]), "r"(b[0]), "r"(b[1]));
}

// ================= prep kernels =================
__global__ void prop_prep(const float* __restrict__ logits, const float* __restrict__ corners) {
    int p = blockIdx.x * blockDim.x + threadIdx.x;
    if (p >= NB*NPROP) return;
    const float* l = logits + (size_t)p * NCLS;
    float best = l[0]; int bi = 0;
    #pragma unroll
    for (int k = 1; k < NCLS; k++) { float v = l[k]; if (v > best) { best = v; bi = k; } }
    g_pmask[p] = (bi != NCLS - 1) ? 1.f : 0.f;
    const float* cr = corners + (size_t)p * 24;
    float mn0 = cr[0], mn1 = cr[1], mn2 = cr[2];
    float mx0 = cr[0], mx1 = cr[1], mx2 = cr[2];
    #pragma unroll
    for (int c = 1; c < 8; c++) {
        float x = cr[c*3+0], y = cr[c*3+1], z = cr[c*3+2];
        mn0 = fminf(mn0, x); mx0 = fmaxf(mx0, x);
        mn1 = fminf(mn1, y); mx1 = fmaxf(mx1, y);
        mn2 = fminf(mn2, z); mx2 = fmaxf(mx2, z);
    }
    g_mn[p*3+0] = mn0; g_mn[p*3+1] = mn1; g_mn[p*3+2] = mn2;
    g_mx[p*3+0] = mx0; g_mx[p*3+1] = mx1; g_mx[p*3+2] = mx2;
    g_vol[p] = (mx0-mn0)*(mx1-mn1)*(mx2-mn2);
}

__global__ void nn_init() {
    int i = blockIdx.x * blockDim.x + threadIdx.x;
    if (i < MROWS) g_nnpack[i] = ~0ull;
}

__global__ void box_match(const float* __restrict__ box_query) {
    __shared__ float s_mn[NPROP*3], s_mx[NPROP*3], s_vol[NPROP], s_msk[NPROP];
    int b = blockIdx.x, t = threadIdx.x;
    if (t < NPROP) {
        int p = b*NPROP + t;
        s_mn[t*3+0] = g_mn[p*3+0]; s_mn[t*3+1] = g_mn[p*3+1]; s_mn[t*3+2] = g_mn[p*3+2];
        s_mx[t*3+0] = g_mx[p*3+0]; s_mx[t*3+1] = g_mx[p*3+1]; s_mx[t*3+2] = g_mx[p*3+2];
        s_vol[t] = g_vol[p]; s_msk[t] = g_pmask[p];
    }
    __syncthreads();
    if (t < NBQ) {
        const float* cq = box_query + ((size_t)b*NBQ + t) * 24;
        float mn0 = cq[0], mn1 = cq[1], mn2 = cq[2];
        float mx0 = cq[0], mx1 = cq[1], mx2 = cq[2];
        #pragma unroll
        for (int c = 1; c < 8; c++) {
            float x = cq[c*3+0], y = cq[c*3+1], z = cq[c*3+2];
            mn0 = fminf(mn0, x); mx0 = fmaxf(mx0, x);
            mn1 = fminf(mn1, y); mx1 = fmaxf(mx1, y);
            mn2 = fminf(mn2, z); mx2 = fmaxf(mx2, z);
        }
        float volq = (mx0-mn0)*(mx1-mn1)*(mx2-mn2);
        float best = -1.f; int bi = 0;
        for (int p = 0; p < NPROP; p++) {
            float ix = fmaxf(fminf(mx0, s_mx[p*3+0]) - fmaxf(mn0, s_mn[p*3+0]), 0.f);
            float iy = fmaxf(fminf(mx1, s_mx[p*3+1]) - fmaxf(mn1, s_mn[p*3+1]), 0.f);
            float iz = fmaxf(fminf(mx2, s_mx[p*3+2]) - fmaxf(mn2, s_mn[p*3+2]), 0.f);
            float inter = ix*iy*iz;
            float iou = inter / (volq + s_vol[p] - inter + 1e-8f) * s_msk[p];
            if (iou > best) { best = iou; bi = p; }
        }
        g_match[b*NBQ + t] = bi;
    }
}

// warp-per-row gather
__global__ void gather_box(const float* __restrict__ prop_features) {
    int warp = (blockIdx.x * blockDim.x + threadIdx.x) >> 5;
    int lane = threadIdx.x & 31;
    if (warp >= MROWS) return;
    int b = warp >> 6;
    int m = g_match[warp];
    const float4* src = (const float4*)(prop_features + ((size_t)b*NPROP + m) * CDIM);
    __half* dst = g_bxA + (size_t)warp * CDIM;
    #pragma unroll
    for (int i = 0; i < 2; i++) {
        float4 v = src[lane + i*32];
        int o = (lane + i*32) * 4;
        dst[o+0] = __float2half_rn(v.x);
        dst[o+1] = __float2half_rn(v.y);
        dst[o+2] = __float2half_rn(v.z);
        dst[o+3] = __float2half_rn(v.w);
    }
}

#define NN_PTS 512
__global__ void click_nn(const float* __restrict__ enc_xyz, const float* __restrict__ click_query) {
    __shared__ float s_xyz[NN_PTS*3];
    int b = blockIdx.x, ck = blockIdx.y, t = threadIdx.x;
    const float* src = enc_xyz + ((size_t)b*NPTS + ck*NN_PTS) * 3;
    for (int i = t; i < NN_PTS*3; i += 256) s_xyz[i] = src[i];
    __syncthreads();
    int warp = t >> 5, lane = t & 31;
    for (int q = warp; q < NCK; q += 8) {
        const float* cq = click_query + ((size_t)b*NCK + q) * 3;
        float cx = cq[0], cy = cq[1], cz = cq[2];
        float best = CUDART_INF_F; int bi = 0;
        for (int p = lane; p < NN_PTS; p += 32) {
            float dx = cx - s_xyz[p*3+0];
            float dy = cy - s_xyz[p*3+1];
            float dz = cz - s_xyz[p*3+2];
            float d = dx*dx + dy*dy + dz*dz;
            if (d < best) { best = d; bi = p; }
        }
        #pragma unroll
        for (int off = 16; off; off >>= 1) {
            float ob = __shfl_xor_sync(0xffffffffu, best, off);
            int   oi = __shfl_xor_sync(0xffffffffu, bi, off);
            if (ob < best || (ob == best && oi < bi)) { best = ob; bi = oi; }
        }
        if (lane == 0) {
            unsigned long long key = ((unsigned long long)__float_as_uint(best) << 32)
                                   | (unsigned)(ck*NN_PTS + bi);
            atomicMin(&g_nnpack[b*NCK + q], key);
        }
    }
}

__global__ void click_build(const float* __restrict__ enc_features,
                            const float* __restrict__ click_query,
                            const float* __restrict__ pc_min,
                            const float* __restrict__ pc_max,
                            const float* __restrict__ gauss) {
    int r = blockIdx.x, t = threadIdx.x;  // 128 threads
    int b = r >> 6;
    int nn = (int)(g_nnpack[r] & 0xffffffffull);
    const float2* src = (const float2*)(enc_features + ((size_t)b*NPTS + nn) * CDIM);
    float2 v = src[t];
    int o = r*2*CDIM + 2*t;
    g_ckA[o+0] = __float2half_rn(v.x);
    g_ckA[o+1] = __float2half_rn(v.y);
    const float* cq = click_query + (size_t)r * 3;
    float pr = 0.f;
    #pragma unroll
    for (int d = 0; d < 3; d++) {
        float x01 = (cq[d] - pc_min[b*3+d]) / (pc_max[b*3+d] - pc_min[b*3+d]);
        pr += x01 * 6.283185307179586f * gauss[d*(CDIM/2) + t];
    }
    g_ckA[r*2*CDIM + CDIM + t]       = __float2half_rn(sinf(pr));
    g_ckA[r*2*CDIM + CDIM + 128 + t] = __float2half_rn(cosf(pr));
}

// transpose + fp16 convert: src [K,N] f32 -> dst [N,K] fp16
__global__ void tconv(const float* __restrict__ src, __half* __restrict__ dh, int K, int N) {
    __shared__ float tile[32][33];
    int n0 = blockIdx.x*32, k0 = blockIdx.y*32;
    int tx = threadIdx.x, ty = threadIdx.y;
    #pragma unroll
    for (int j = 0; j < 4; j++)
        tile[ty + 8*j][tx] = src[(size_t)(k0 + ty + 8*j) * N + n0 + tx];
    __syncthreads();
    #pragma unroll
    for (int j = 0; j < 4; j++)
        dh[(size_t)(n0 + ty + 8*j) * K + k0 + tx] = __float2half_rn(tile[tx][ty + 8*j]);
}

// ================= HMMA GEMM =================
// 128x128 CTA tile, BK=32, 8 warps (2M x 4N), warp tile 64x32, 2 smem tiles,
// 3-stage cp.async ring, one __syncthreads per slab, occ 2.
#define ROWB 80
#define TILE_B (128*ROWB)            // 10240
#define STAGE_B (2*TILE_B)           // 20480
#define NSTAGE 3
#define SMEM_G (NSTAGE*STAGE_B + 512)  // 61952

__device__ __forceinline__ void gemm_body(
        const __half* __restrict__ A, const __half* __restrict__ B,
        int K, int m0, int n0, uint32_t base, int t, float acc[4][4][4]) {
    const int lid = t & 31;
    const int mwarp = (t >> 5) & 1, nwarp = t >> 6;
    const int S = K >> 5;

    auto load_slab = [&](int s) {
        uint32_t sb = base + (s % NSTAGE) * STAGE_B;
        size_t kof = (size_t)s * 32;
        #pragma unroll
        for (int i = 0; i < 4; i++) {
            int c = i * 256 + t;
            int tile = c >> 9, local = c & 511;
            int row = local >> 2, chk = local & 3;
            uint32_t dst = sb + tile * TILE_B + row * ROWB + chk * 16;
            const __half* srcp = (tile == 0)
                ? A + (size_t)(m0 + row) * K + kof + chk * 8
                : B + (size_t)(n0 + row) * K + kof + chk * 8;
            cp16(dst, srcp);
        }
    };
    auto compute_stage = [&](int s) {
        uint32_t sb = base + (s % NSTAGE) * STAGE_B;
        uint32_t aP = sb, bP = sb + TILE_B;
        #pragma unroll
        for (int ks = 0; ks < 32; ks += 16) {
            uint32_t ah[4][4], bh[4][2];
            uint32_t aoff = (uint32_t)((mwarp*64 + (lid & 15)) * ROWB
                                       + (ks + ((lid >> 4) << 3)) * 2);
            #pragma unroll
            for (int mi = 0; mi < 4; mi++)
                ldsm_x4(ah[mi], aP + aoff + mi*16*ROWB);
            uint32_t boff = (uint32_t)((nwarp*32 + (lid & 7)) * ROWB
                                       + (ks + (((lid >> 3) & 1) << 3)) * 2);
            #pragma unroll
            for (int ni = 0; ni < 4; ni++)
                ldsm_x2(bh[ni], bP + boff + ni*8*ROWB);
            #pragma unroll
            for (int mi = 0; mi < 4; mi++)
                #pragma unroll
                for (int ni = 0; ni < 4; ni++)
                    mma16816(acc[mi][ni], ah[mi], bh[ni]);
        }
    };

    load_slab(0); CP_COMMIT();
    if (S > 1) load_slab(1);
    CP_COMMIT();
    for (int s = 0; s < S; s++) {
        CP_WAIT1();
        __syncthreads();
        if (s + 2 < S) load_slab(s + 2);
        CP_COMMIT();
        compute_stage(s);
    }
}

// layer 1 (both branches via blockIdx.z): relu(D+bias) -> fp16 hidden
__global__ __launch_bounds__(256, 2) void tgemm_l1(
        const __half* A0, const __half* B0, const float* b0, int K0, __half* H0,
        const __half* A1, const __half* B1, const float* b1, int K1, __half* H1) {
    extern __shared__ __align__(16) char smem_raw[];
    const uint32_t base = smem_u32(smem_raw);
    float* s_bias = (float*)(smem_raw + NSTAGE * STAGE_B);
    int z = blockIdx.z, t = threadIdx.x;
    const __half* A = z ? A1 : A0;
    const __half* B = z ? B1 : B0;
    const float* bias = z ? b1 : b0;
    int K = z ? K1 : K0;
    __half* H = z ? H1 : H0;
    int m0 = blockIdx.y * 128, n0 = blockIdx.x * 128;
    if (t < 128) s_bias[t] = bias[n0 + t];

    float acc[4][4][4];
    #pragma unroll
    for (int mi = 0; mi < 4; mi++)
        #pragma unroll
        for (int ni = 0; ni < 4; ni++)
            #pragma unroll
            for (int r = 0; r < 4; r++) acc[mi][ni][r] = 0.f;

    gemm_body(A, B, K, m0, n0, base, t, acc);

    const int lid = t & 31;
    const int mb = m0 + ((t >> 5) & 1) * 64;
    const int nb = n0 + (t >> 6) * 32;
    #pragma unroll
    for (int mi = 0; mi < 4; mi++) {
        int r0 = mb + mi*16 + (lid >> 2);
        #pragma unroll
        for (int ni = 0; ni < 4; ni++) {
            int n = nb + ni*8 + (lid & 3)*2;
            float v00 = fmaxf(acc[mi][ni][0] + s_bias[n   - n0], 0.f);
            float v01 = fmaxf(acc[mi][ni][1] + s_bias[n+1 - n0], 0.f);
            float v10 = fmaxf(acc[mi][ni][2] + s_bias[n   - n0], 0.f);
            float v11 = fmaxf(acc[mi][ni][3] + s_bias[n+1 - n0], 0.f);
            size_t o0 = (size_t)r0 * QHD + n;
            size_t o1 = (size_t)(r0 + 8) * QHD + n;
            H[o0]   = __float2half_rn(v00);
            H[o0+1] = __float2half_rn(v01);
            H[o1]   = __float2half_rn(v10);
            H[o1+1] = __float2half_rn(v11);
        }
    }
}

// layer 2 (both branches via blockIdx.z): D+bias -> out remapped (b,q,v,h)
__global__ __launch_bounds__(256, 2) void tgemm_l2(
        const __half* A0, const __half* B0, const float* b0,
        const __half* A1, const __half* B1, const float* b1,
        float* __restrict__ outf) {
    extern __shared__ __align__(16) char smem_raw[];
    const uint32_t base = smem_u32(smem_raw);
    float* s_bias = (float*)(smem_raw + NSTAGE * STAGE_B);
    int z = blockIdx.z, t = threadIdx.x;
    const __half* A = z ? A1 : A0;
    const __half* B = z ? B1 : B0;
    const float* bias = z ? b1 : b0;
    int m0 = blockIdx.y * 128, n0 = blockIdx.x * 128;
    if (t < 128) s_bias[t] = bias[n0 + t];

    float acc[4][4][4];
    #pragma unroll
    for (int mi = 0; mi < 4; mi++)
        #pragma unroll
        for (int ni = 0; ni < 4; ni++)
            #pragma unroll
            for (int r = 0; r < 4; r++) acc[mi][ni][r] = 0.f;

    gemm_body(A, B, QHD, m0, n0, base, t, acc);

    const int lid = t & 31;
    const int mb = m0 + ((t >> 5) & 1) * 64;
    const int nb = n0 + (t >> 6) * 32;
    const int boff = z ? (NBQ * VQn) : 0;
    #pragma unroll
    for (int mi = 0; mi < 4; mi++) {
        int r0 = mb + mi*16 + (lid >> 2);
        #pragma unroll
        for (int ni = 0; ni < 4; ni++) {
            int n = nb + ni*8 + (lid & 3)*2;
            float v00 = acc[mi][ni][0] + s_bias[n   - n0];
            float v01 = acc[mi][ni][1] + s_bias[n+1 - n0];
            float v10 = acc[mi][ni][2] + s_bias[n   - n0];
            float v11 = acc[mi][ni][3] + s_bias[n+1 - n0];
            int vq = n / QHD, h = n - vq * QHD;
            int b0i = r0 >> 6, q0 = r0 & 63;
            int r1 = r0 + 8;
            int b1i = r1 >> 6, q1 = r1 & 63;
            size_t o0 = ((size_t)(b0i*OUTROWS + boff + q0*VQn + vq)) * QHD + h;
            size_t o1 = ((size_t)(b1i*OUTROWS + boff + q1*VQn + vq)) * QHD + h;
            outf[o0]   = v00; outf[o0+1] = v01;
            outf[o1]   = v10; outf[o1+1] = v11;
        }
    }
}

__global__ void write_mask(const float* __restrict__ box_qmask,
                           const float* __restrict__ click_qmask,
                           float* __restrict__ out_mask) {
    int i = blockIdx.x * blockDim.x + threadIdx.x;
    if (i >= NB * OUTROWS) return;
    int b = i >> 10, r = i & 1023;
    float v = (r < NBQ*VQn) ? box_qmask[b*NBQ + (r >> 3)]
                            : click_qmask[b*NCK + ((r - NBQ*VQn) >> 3)];
    out_mask[i] = v;
}

// ================= host =================
extern "C" void kernel_launch(void* const* d_in, const int* in_sizes, int n_in,
                              void* d_out, int out_size) {
    const float* sem     = (const float*)d_in[0];
    const float* propf   = (const float*)d_in[1];
    const float* boxc    = (const float*)d_in[2];
    const float* encxyz  = (const float*)d_in[3];
    const float* encf    = (const float*)d_in[4];
    const float* pcmin   = (const float*)d_in[5];
    const float* pcmax   = (const float*)d_in[6];
    const float* boxq    = (const float*)d_in[7];
    const float* boxqm   = (const float*)d_in[8];
    const float* clickq  = (const float*)d_in[9];
    const float* clickqm = (const float*)d_in[10];
    const float* gauss   = (const float*)d_in[11];
    const float* bw1     = (const float*)d_in[12];
    const float* bb1     = (const float*)d_in[13];
    const float* bw2     = (const float*)d_in[14];
    const float* bb2     = (const float*)d_in[15];
    const float* cw1     = (const float*)d_in[16];
    const float* cb1     = (const float*)d_in[17];
    const float* cw2     = (const float*)d_in[18];
    const float* cb2     = (const float*)d_in[19];
    float* out = (float*)d_out;

    void *bxA, *ckA, *w1b, *w1c, *w2b, *w2c, *h1, *h2;
    cudaGetSymbolAddress(&bxA, g_bxA); cudaGetSymbolAddress(&ckA, g_ckA);
    cudaGetSymbolAddress(&w1b, g_w1b); cudaGetSymbolAddress(&w1c, g_w1c);
    cudaGetSymbolAddress(&w2b, g_w2b); cudaGetSymbolAddress(&w2c, g_w2c);
    cudaGetSymbolAddress(&h1,  g_h1);  cudaGetSymbolAddress(&h2,  g_h2);

    cudaFuncSetAttribute(tgemm_l1, cudaFuncAttributeMaxDynamicSharedMemorySize, SMEM_G);
    cudaFuncSetAttribute(tgemm_l2, cudaFuncAttributeMaxDynamicSharedMemorySize, SMEM_G);

    prop_prep<<<(NB*NPROP + 127)/128, 128>>>(sem, boxc);
    nn_init<<<(MROWS + 255)/256, 256>>>();
    box_match<<<NB, 256>>>(boxq);
    gather_box<<<MROWS/8, 256>>>(propf);
    click_nn<<<dim3(NB, NPTS/NN_PTS), 256>>>(encxyz, clickq);
    click_build<<<MROWS, 128>>>(encf, clickq, pcmin, pcmax, gauss);

    {
        dim3 blk(32, 8);
        tconv<<<dim3(QHD/32, CDIM/32),    blk>>>(bw1, (__half*)w1b, CDIM,   QHD);
        tconv<<<dim3(QHD/32, 2*CDIM/32),  blk>>>(cw1, (__half*)w1c, 2*CDIM, QHD);
        tconv<<<dim3(VQn*QHD/32, QHD/32), blk>>>(bw2, (__half*)w2b, QHD, VQn*QHD);
        tconv<<<dim3(VQn*QHD/32, QHD/32), blk>>>(cw2, (__half*)w2c, QHD, VQn*QHD);
    }

    // layer 1: both branches in one launch (z=2), M=2048, N=768
    tgemm_l1<<<dim3(QHD/128, MROWS/128, 2), 256, SMEM_G>>>(
        (__half*)bxA, (__half*)w1b, bb1, CDIM,   (__half*)h1,
        (__half*)ckA, (__half*)w1c, cb1, 2*CDIM, (__half*)h2);

    // layer 2: both branches in one launch (z=2), M=2048, N=6144
    tgemm_l2<<<dim3(VQn*QHD/128, MROWS/128, 2), 256, SMEM_G>>>(
        (__half*)h1, (__half*)w2b, bb2,
        (__half*)h2, (__half*)w2c, cb2, out);

    write_mask<<<(NB*OUTROWS + 255)/256, 256>>>(boxqm, clickqm, out + FEAT_ELEMS);
}

// round 12
// speedup vs baseline: 1.1966x; 1.0711x over previous
#include <cuda_runtime.h>
#include <cuda_fp16.h>
#include <math_constants.h>
#include <cstdint>

#define NB 32
#define NPROP 256
#define NCLS 19
#define NPTS 4096
#define NBQ 64
#define NCK 64
#define CDIM 256
#define QHD 768
#define VQn 8
#define MROWS (NB*NBQ)                 // 2048
#define OUTROWS 1024
#define FEAT_ELEMS (NB*OUTROWS*QHD)    // 25165824

// ================= device scratch =================
__device__ int   g_match[MROWS];
__device__ unsigned long long g_nnkey[MROWS*8];   // per-chunk NN keys

__device__ __half g_bxA[MROWS*CDIM];        // [2048,256]
__device__ __half g_ckA[MROWS*2*CDIM];      // [2048,512]
__device__ __half g_w1b[QHD*CDIM];          // [768,256]  (N,K)
__device__ __half g_w1c[QHD*2*CDIM];        // [768,512]
__device__ __half g_w2b[VQn*QHD*QHD];       // [6144,768]
__device__ __half g_w2c[VQn*QHD*QHD];       // [6144,768]
__device__ __half g_h1[MROWS*QHD];          // box hidden fp16
__device__ __half g_h2[MROWS*QHD];          // click hidden fp16

// ================= helpers =================
__device__ __forceinline__ uint32_t smem_u32(const void* p) {
    uint32_t a;
    asm("{ .reg .u64 t; cvta.to.shared.u64 t, %1; cvt.u32.u64 %0, t; }" : "=r"(a) : "l"(p));
    return a;
}
__device__ __forceinline__ void cp16(uint32_t dst, const void* src) {
    asm volatile("cp.async.cg.shared.global [%0], [%1], 16;" :: "r"(dst), "l"(src));
}
#define CP_COMMIT() asm volatile("cp.async.commit_group;" ::: "memory")
#define CP_WAIT1()  asm volatile("cp.async.wait_group 1;" ::: "memory")

__device__ __forceinline__ void ldsm_x4(uint32_t* r, uint32_t addr) {
    asm volatile("ldmatrix.sync.aligned.m8n8.x4.shared.b16 {%0,%1,%2,%3}, [%4];"
        : "=r"(r[0]), "=r"(r[1]), "=r"(r[2]), "=r"(r[3]) : "r"(addr));
}
__device__ __forceinline__ void ldsm_x2(uint32_t* r, uint32_t addr) {
    asm volatile("ldmatrix.sync.aligned.m8n8.x2.shared.b16 {%0,%1}, [%2];"
        : "=r"(r[0]), "=r"(r[1]) : "r"(addr));
}
__device__ __forceinline__ void mma16816(float* d, const uint32_t* a, const uint32_t* b) {
    asm volatile(
        "mma.sync.aligned.m16n8k16.row.col.f32.f16.f16.f32 "
        "{%0,%1,%2,%3}, {%4,%5,%6,%7}, {%8,%9}, {%0,%1,%2,%3};"
        : "+f"(d[0]), "+f"(d[1]), "+f"(d[2]), "+f"(d[3])
        : "r"(a[0]), "r"(a[1]), "r"(a[2]), "r"(a[3]), "r"(b[0]), "r"(b[1]));
}

// ================= prep kernels =================
// fused: per-proposal argmax/AABB (256 threads) + IoU argmax match (64 threads)
__global__ void box_prep_match(const float* __restrict__ logits,
                               const float* __restrict__ corners,
                               const float* __restrict__ box_query) {
    __shared__ float s_mn[NPROP*3], s_mx[NPROP*3], s_vol[NPROP], s_msk[NPROP];
    int b = blockIdx.x, t = threadIdx.x;
    {
        int p = b*NPROP + t;
        const float* l = logits + (size_t)p * NCLS;
        float best = l[0]; int bi = 0;
        #pragma unroll
        for (int k = 1; k < NCLS; k++) { float v = l[k]; if (v > best) { best = v; bi = k; } }
        s_msk[t] = (bi != NCLS - 1) ? 1.f : 0.f;
        const float* cr = corners + (size_t)p * 24;
        float mn0 = cr[0], mn1 = cr[1], mn2 = cr[2];
        float mx0 = cr[0], mx1 = cr[1], mx2 = cr[2];
        #pragma unroll
        for (int c = 1; c < 8; c++) {
            float x = cr[c*3+0], y = cr[c*3+1], z = cr[c*3+2];
            mn0 = fminf(mn0, x); mx0 = fmaxf(mx0, x);
            mn1 = fminf(mn1, y); mx1 = fmaxf(mx1, y);
            mn2 = fminf(mn2, z); mx2 = fmaxf(mx2, z);
        }
        s_mn[t*3+0] = mn0; s_mn[t*3+1] = mn1; s_mn[t*3+2] = mn2;
        s_mx[t*3+0] = mx0; s_mx[t*3+1] = mx1; s_mx[t*3+2] = mx2;
        s_vol[t] = (mx0-mn0)*(mx1-mn1)*(mx2-mn2);
    }
    __syncthreads();
    if (t < NBQ) {
        const float* cq = box_query + ((size_t)b*NBQ + t) * 24;
        float mn0 = cq[0], mn1 = cq[1], mn2 = cq[2];
        float mx0 = cq[0], mx1 = cq[1], mx2 = cq[2];
        #pragma unroll
        for (int c = 1; c < 8; c++) {
            float x = cq[c*3+0], y = cq[c*3+1], z = cq[c*3+2];
            mn0 = fminf(mn0, x); mx0 = fmaxf(mx0, x);
            mn1 = fminf(mn1, y); mx1 = fmaxf(mx1, y);
            mn2 = fminf(mn2, z); mx2 = fmaxf(mx2, z);
        }
        float volq = (mx0-mn0)*(mx1-mn1)*(mx2-mn2);
        float best = -1.f; int bi = 0;
        for (int p = 0; p < NPROP; p++) {
            float ix = fmaxf(fminf(mx0, s_mx[p*3+0]) - fmaxf(mn0, s_mn[p*3+0]), 0.f);
            float iy = fmaxf(fminf(mx1, s_mx[p*3+1]) - fmaxf(mn1, s_mn[p*3+1]), 0.f);
            float iz = fmaxf(fminf(mx2, s_mx[p*3+2]) - fmaxf(mn2, s_mn[p*3+2]), 0.f);
            float inter = ix*iy*iz;
            float iou = inter / (volq + s_vol[p] - inter + 1e-8f) * s_msk[p];
            if (iou > best) { best = iou; bi = p; }
        }
        g_match[b*NBQ + t] = bi;
    }
}

// warp-per-row gather
__global__ void gather_box(const float* __restrict__ prop_features) {
    int warp = (blockIdx.x * blockDim.x + threadIdx.x) >> 5;
    int lane = threadIdx.x & 31;
    if (warp >= MROWS) return;
    int b = warp >> 6;
    int m = g_match[warp];
    const float4* src = (const float4*)(prop_features + ((size_t)b*NPROP + m) * CDIM);
    __half* dst = g_bxA + (size_t)warp * CDIM;
    #pragma unroll
    for (int i = 0; i < 2; i++) {
        float4 v = src[lane + i*32];
        int o = (lane + i*32) * 4;
        dst[o+0] = __float2half_rn(v.x);
        dst[o+1] = __float2half_rn(v.y);
        dst[o+2] = __float2half_rn(v.z);
        dst[o+3] = __float2half_rn(v.w);
    }
}

#define NN_PTS 512
__global__ void click_nn(const float* __restrict__ enc_xyz, const float* __restrict__ click_query) {
    __shared__ float s_xyz[NN_PTS*3];
    int b = blockIdx.x, ck = blockIdx.y, t = threadIdx.x;
    const float* src = enc_xyz + ((size_t)b*NPTS + ck*NN_PTS) * 3;
    for (int i = t; i < NN_PTS*3; i += 256) s_xyz[i] = src[i];
    __syncthreads();
    int warp = t >> 5, lane = t & 31;
    for (int q = warp; q < NCK; q += 8) {
        const float* cq = click_query + ((size_t)b*NCK + q) * 3;
        float cx = cq[0], cy = cq[1], cz = cq[2];
        float best = CUDART_INF_F; int bi = 0;
        for (int p = lane; p < NN_PTS; p += 32) {
            float dx = cx - s_xyz[p*3+0];
            float dy = cy - s_xyz[p*3+1];
            float dz = cz - s_xyz[p*3+2];
            float d = dx*dx + dy*dy + dz*dz;
            if (d < best) { best = d; bi = p; }
        }
        #pragma unroll
        for (int off = 16; off; off >>= 1) {
            float ob = __shfl_xor_sync(0xffffffffu, best, off);
            int   oi = __shfl_xor_sync(0xffffffffu, bi, off);
            if (ob < best || (ob == best && oi < bi)) { best = ob; bi = oi; }
        }
        if (lane == 0)
            g_nnkey[(b*NCK + q)*8 + ck] =
                ((unsigned long long)__float_as_uint(best) << 32)
                | (unsigned)(ck*NN_PTS + bi);
    }
}

__global__ void click_build(const float* __restrict__ enc_features,
                            const float* __restrict__ click_query,
                            const float* __restrict__ pc_min,
                            const float* __restrict__ pc_max,
                            const float* __restrict__ gauss) {
    int r = blockIdx.x, t = threadIdx.x;  // 128 threads
    int b = r >> 6;
    unsigned long long key = ~0ull;
    #pragma unroll
    for (int ck = 0; ck < 8; ck++) {
        unsigned long long k = g_nnkey[r*8 + ck];
        if (k < key) key = k;
    }
    int nn = (int)(key & 0xffffffffull);
    const float2* src = (const float2*)(enc_features + ((size_t)b*NPTS + nn) * CDIM);
    float2 v = src[t];
    int o = r*2*CDIM + 2*t;
    g_ckA[o+0] = __float2half_rn(v.x);
    g_ckA[o+1] = __float2half_rn(v.y);
    const float* cq = click_query + (size_t)r * 3;
    float pr = 0.f;
    #pragma unroll
    for (int d = 0; d < 3; d++) {
        float x01 = (cq[d] - pc_min[b*3+d]) / (pc_max[b*3+d] - pc_min[b*3+d]);
        pr += x01 * 6.283185307179586f * gauss[d*(CDIM/2) + t];
    }
    g_ckA[r*2*CDIM + CDIM + t]       = __float2half_rn(sinf(pr));
    g_ckA[r*2*CDIM + CDIM + 128 + t] = __float2half_rn(cosf(pr));
}

// merged transpose + fp16 convert for all 4 weights
// segmented grid: [0,192) w1b, [192,576) w1c, [576,5184) w2b, [5184,9792) w2c
__global__ void tconv_all(const float* __restrict__ bw1, const float* __restrict__ cw1,
                          const float* __restrict__ bw2, const float* __restrict__ cw2,
                          __half* __restrict__ dw1b, __half* __restrict__ dw1c,
                          __half* __restrict__ dw2b, __half* __restrict__ dw2c) {
    __shared__ float tile[32][33];
    int u = blockIdx.x;
    const float* src; __half* dst; int K, N, nx;
    if      (u < 192)  { src = bw1; dst = dw1b; K = CDIM;   N = QHD;     nx = 24;  }
    else if (u < 576)  { src = cw1; dst = dw1c; K = 2*CDIM; N = QHD;     nx = 24;  u -= 192; }
    else if (u < 5184) { src = bw2; dst = dw2b; K = QHD;    N = VQn*QHD; nx = 192; u -= 576; }
    else               { src = cw2; dst = dw2c; K = QHD;    N = VQn*QHD; nx = 192; u -= 5184; }
    int n0 = (u % nx) * 32, k0 = (u / nx) * 32;
    int tx = threadIdx.x, ty = threadIdx.y;
    #pragma unroll
    for (int j = 0; j < 4; j++)
        tile[ty + 8*j][tx] = src[(size_t)(k0 + ty + 8*j) * N + n0 + tx];
    __syncthreads();
    #pragma unroll
    for (int j = 0; j < 4; j++)
        dst[(size_t)(n0 + ty + 8*j) * K + k0 + tx] = __float2half_rn(tile[tx][ty + 8*j]);
}

// ================= layer-1 GEMM (proven R10 geometry) =================
// 128x128 CTA tile, BK=32, warp 64x32, 3-stage ring, occ 2.
#define ROWB 80
#define TILE_B (128*ROWB)              // 10240
#define STAGE_B (2*TILE_B)             // 20480
#define NSTAGE 3
#define SMEM_L1 (NSTAGE*STAGE_B + 512) // 61952

__device__ __forceinline__ void gemm_body128(
        const __half* __restrict__ A, const __half* __restrict__ B,
        int K, int m0, int n0, uint32_t base, int t, float acc[4][4][4]) {
    const int lid = t & 31;
    const int mwarp = (t >> 5) & 1, nwarp = t >> 6;
    const int S = K >> 5;

    auto load_slab = [&](int s) {
        uint32_t sb = base + (s % NSTAGE) * STAGE_B;
        size_t kof = (size_t)s * 32;
        #pragma unroll
        for (int i = 0; i < 4; i++) {
            int c = i * 256 + t;
            int tile = c >> 9, local = c & 511;
            int row = local >> 2, chk = local & 3;
            uint32_t dst = sb + tile * TILE_B + row * ROWB + chk * 16;
            const __half* srcp = (tile == 0)
                ? A + (size_t)(m0 + row) * K + kof + chk * 8
                : B + (size_t)(n0 + row) * K + kof + chk * 8;
            cp16(dst, srcp);
        }
    };
    auto compute_stage = [&](int s) {
        uint32_t sb = base + (s % NSTAGE) * STAGE_B;
        uint32_t aP = sb, bP = sb + TILE_B;
        #pragma unroll
        for (int ks = 0; ks < 32; ks += 16) {
            uint32_t ah[4][4], bh[4][2];
            uint32_t aoff = (uint32_t)((mwarp*64 + (lid & 15)) * ROWB
                                       + (ks + ((lid >> 4) << 3)) * 2);
            #pragma unroll
            for (int mi = 0; mi < 4; mi++)
                ldsm_x4(ah[mi], aP + aoff + mi*16*ROWB);
            uint32_t boff = (uint32_t)((nwarp*32 + (lid & 7)) * ROWB
                                       + (ks + (((lid >> 3) & 1) << 3)) * 2);
            #pragma unroll
            for (int ni = 0; ni < 4; ni++)
                ldsm_x2(bh[ni], bP + boff + ni*8*ROWB);
            #pragma unroll
            for (int mi = 0; mi < 4; mi++)
                #pragma unroll
                for (int ni = 0; ni < 4; ni++)
                    mma16816(acc[mi][ni], ah[mi], bh[ni]);
        }
    };

    load_slab(0); CP_COMMIT();
    if (S > 1) load_slab(1);
    CP_COMMIT();
    for (int s = 0; s < S; s++) {
        CP_WAIT1();
        __syncthreads();
        if (s + 2 < S) load_slab(s + 2);
        CP_COMMIT();
        compute_stage(s);
    }
}

__global__ __launch_bounds__(256, 2) void tgemm_l1(
        const __half* A0, const __half* B0, const float* b0, int K0, __half* H0,
        const __half* A1, const __half* B1, const float* b1, int K1, __half* H1) {
    extern __shared__ __align__(16) char smem_raw[];
    const uint32_t base = smem_u32(smem_raw);
    float* s_bias = (float*)(smem_raw + NSTAGE * STAGE_B);
    int z = blockIdx.z, t = threadIdx.x;
    const __half* A = z ? A1 : A0;
    const __half* B = z ? B1 : B0;
    const float* bias = z ? b1 : b0;
    int K = z ? K1 : K0;
    __half* H = z ? H1 : H0;
    int m0 = blockIdx.y * 128, n0 = blockIdx.x * 128;
    if (t < 128) s_bias[t] = bias[n0 + t];

    float acc[4][4][4];
    #pragma unroll
    for (int mi = 0; mi < 4; mi++)
        #pragma unroll
        for (int ni = 0; ni < 4; ni++)
            #pragma unroll
            for (int r = 0; r < 4; r++) acc[mi][ni][r] = 0.f;

    gemm_body128(A, B, K, m0, n0, base, t, acc);

    const int lid = t & 31;
    const int mb = m0 + ((t >> 5) & 1) * 64;
    const int nb = n0 + (t >> 6) * 32;
    #pragma unroll
    for (int mi = 0; mi < 4; mi++) {
        int r0 = mb + mi*16 + (lid >> 2);
        #pragma unroll
        for (int ni = 0; ni < 4; ni++) {
            int n = nb + ni*8 + (lid & 3)*2;
            float v00 = fmaxf(acc[mi][ni][0] + s_bias[n   - n0], 0.f);
            float v01 = fmaxf(acc[mi][ni][1] + s_bias[n+1 - n0], 0.f);
            float v10 = fmaxf(acc[mi][ni][2] + s_bias[n   - n0], 0.f);
            float v11 = fmaxf(acc[mi][ni][3] + s_bias[n+1 - n0], 0.f);
            size_t o0 = (size_t)r0 * QHD + n;
            size_t o1 = (size_t)(r0 + 8) * QHD + n;
            H[o0]   = __float2half_rn(v00);
            H[o0+1] = __float2half_rn(v01);
            H[o1]   = __float2half_rn(v10);
            H[o1+1] = __float2half_rn(v11);
        }
    }
}

// ================= layer-2 GEMM: 128x96 tile, BK=64, 3-stage =================
// grid 64x16x2 = 2048 CTAs -> 6.92 waves (1% quantization waste).
// warp tile 64x24 (2M x 4N warps). ROWB2=144 (conflict-free: stride 36 banks).
#define ROWB2 144
#define L2_AT (128*ROWB2)              // 18432
#define L2_BT (96*ROWB2)               // 13824
#define L2_STAGE (L2_AT + L2_BT)       // 32256
#define SMEM_L2 (NSTAGE*L2_STAGE + 512) // 97280

__global__ __launch_bounds__(256, 2) void tgemm_l2(
        const __half* A0, const __half* B0, const float* b0,
        const __half* A1, const __half* B1, const float* b1,
        float* __restrict__ outf) {
    extern __shared__ __align__(16) char smem_raw[];
    const uint32_t base = smem_u32(smem_raw);
    float* s_bias = (float*)(smem_raw + NSTAGE * L2_STAGE);
    int z = blockIdx.z, t = threadIdx.x;
    const __half* A = z ? A1 : A0;
    const __half* B = z ? B1 : B0;
    const float* bias = z ? b1 : b0;
    const int K = QHD;
    int m0 = blockIdx.y * 128, n0 = blockIdx.x * 96;
    if (t < 96) s_bias[t] = bias[n0 + t];

    const int lid = t & 31;
    const int mwarp = (t >> 5) & 1, nwarp = t >> 6;

    float acc[4][3][4];
    #pragma unroll
    for (int mi = 0; mi < 4; mi++)
        #pragma unroll
        for (int ni = 0; ni < 3; ni++)
            #pragma unroll
            for (int r = 0; r < 4; r++) acc[mi][ni][r] = 0.f;

    auto load_slab = [&](int s) {
        uint32_t sb = base + (s % NSTAGE) * L2_STAGE;
        size_t kof = (size_t)s * 64;
        #pragma unroll
        for (int i = 0; i < 4; i++) {          // A: 128 rows x 8 chunks = 1024
            int c = i * 256 + t;
            int row = c >> 3, chk = c & 7;
            cp16(sb + row * ROWB2 + chk * 16,
                 A + (size_t)(m0 + row) * K + kof + chk * 8);
        }
        #pragma unroll
        for (int i = 0; i < 3; i++) {          // B: 96 rows x 8 chunks = 768
            int c = i * 256 + t;
            int row = c >> 3, chk = c & 7;
            cp16(sb + L2_AT + row * ROWB2 + chk * 16,
                 B + (size_t)(n0 + row) * K + kof + chk * 8);
        }
    };
    auto compute_stage = [&](int s) {
        uint32_t sb = base + (s % NSTAGE) * L2_STAGE;
        uint32_t aP = sb, bP = sb + L2_AT;
        #pragma unroll
        for (int ks = 0; ks < 64; ks += 16) {
            uint32_t ah[4][4], bh[3][2];
            uint32_t aoff = (uint32_t)((mwarp*64 + (lid & 15)) * ROWB2
                                       + (ks + ((lid >> 4) << 3)) * 2);
            #pragma unroll
            for (int mi = 0; mi < 4; mi++)
                ldsm_x4(ah[mi], aP + aoff + mi*16*ROWB2);
            uint32_t boff = (uint32_t)((nwarp*24 + (lid & 7)) * ROWB2
                                       + (ks + (((lid >> 3) & 1) << 3)) * 2);
            #pragma unroll
            for (int ni = 0; ni < 3; ni++)
                ldsm_x2(bh[ni], bP + boff + ni*8*ROWB2);
            #pragma unroll
            for (int mi = 0; mi < 4; mi++)
                #pragma unroll
                for (int ni = 0; ni < 3; ni++)
                    mma16816(acc[mi][ni], ah[mi], bh[ni]);
        }
    };

    const int S = K >> 6;                      // 12 slabs
    load_slab(0); CP_COMMIT();
    load_slab(1); CP_COMMIT();
    for (int s = 0; s < S; s++) {
        CP_WAIT1();
        __syncthreads();
        if (s + 2 < S) load_slab(s + 2);
        CP_COMMIT();
        compute_stage(s);
    }

    const int mb = m0 + mwarp * 64;
    const int nb = n0 + nwarp * 24;
    const int boff = z ? (NBQ * VQn) : 0;
    #pragma unroll
    for (int mi = 0; mi < 4; mi++) {
        int r0 = mb + mi*16 + (lid >> 2);
        #pragma unroll
        for (int ni = 0; ni < 3; ni++) {
            int n = nb + ni*8 + (lid & 3)*2;
            float v00 = acc[mi][ni][0] + s_bias[n   - n0];
            float v01 = acc[mi][ni][1] + s_bias[n+1 - n0];
            float v10 = acc[mi][ni][2] + s_bias[n   - n0];
            float v11 = acc[mi][ni][3] + s_bias[n+1 - n0];
            int vq = n / QHD, h = n - vq * QHD;
            int b0i = r0 >> 6, q0 = r0 & 63;
            int r1 = r0 + 8;
            int b1i = r1 >> 6, q1 = r1 & 63;
            size_t o0 = ((size_t)(b0i*OUTROWS + boff + q0*VQn + vq)) * QHD + h;
            size_t o1 = ((size_t)(b1i*OUTROWS + boff + q1*VQn + vq)) * QHD + h;
            outf[o0]   = v00; outf[o0+1] = v01;
            outf[o1]   = v10; outf[o1+1] = v11;
        }
    }
}

__global__ void write_mask(const float* __restrict__ box_qmask,
                           const float* __restrict__ click_qmask,
                           float* __restrict__ out_mask) {
    int i = blockIdx.x * blockDim.x + threadIdx.x;
    if (i >= NB * OUTROWS) return;
    int b = i >> 10, r = i & 1023;
    float v = (r < NBQ*VQn) ? box_qmask[b*NBQ + (r >> 3)]
                            : click_qmask[b*NCK + ((r - NBQ*VQn) >> 3)];
    out_mask[i] = v;
}

// ================= host =================
extern "C" void kernel_launch(void* const* d_in, const int* in_sizes, int n_in,
                              void* d_out, int out_size) {
    const float* sem     = (const float*)d_in[0];
    const float* propf   = (const float*)d_in[1];
    const float* boxc    = (const float*)d_in[2];
    const float* encxyz  = (const float*)d_in[3];
    const float* encf    = (const float*)d_in[4];
    const float* pcmin   = (const float*)d_in[5];
    const float* pcmax   = (const float*)d_in[6];
    const float* boxq    = (const float*)d_in[7];
    const float* boxqm   = (const float*)d_in[8];
    const float* clickq  = (const float*)d_in[9];
    const float* clickqm = (const float*)d_in[10];
    const float* gauss   = (const float*)d_in[11];
    const float* bw1     = (const float*)d_in[12];
    const float* bb1     = (const float*)d_in[13];
    const float* bw2     = (const float*)d_in[14];
    const float* bb2     = (const float*)d_in[15];
    const float* cw1     = (const float*)d_in[16];
    const float* cb1     = (const float*)d_in[17];
    const float* cw2     = (const float*)d_in[18];
    const float* cb2     = (const float*)d_in[19];
    float* out = (float*)d_out;

    void *bxA, *ckA, *w1b, *w1c, *w2b, *w2c, *h1, *h2;
    cudaGetSymbolAddress(&bxA, g_bxA); cudaGetSymbolAddress(&ckA, g_ckA);
    cudaGetSymbolAddress(&w1b, g_w1b); cudaGetSymbolAddress(&w1c, g_w1c);
    cudaGetSymbolAddress(&w2b, g_w2b); cudaGetSymbolAddress(&w2c, g_w2c);
    cudaGetSymbolAddress(&h1,  g_h1);  cudaGetSymbolAddress(&h2,  g_h2);

    cudaFuncSetAttribute(tgemm_l1, cudaFuncAttributeMaxDynamicSharedMemorySize, SMEM_L1);
    cudaFuncSetAttribute(tgemm_l2, cudaFuncAttributeMaxDynamicSharedMemorySize, SMEM_L2);

    box_prep_match<<<NB, 256>>>(sem, boxc, boxq);
    gather_box<<<MROWS/8, 256>>>(propf);
    click_nn<<<dim3(NB, NPTS/NN_PTS), 256>>>(encxyz, clickq);
    click_build<<<MROWS, 128>>>(encf, clickq, pcmin, pcmax, gauss);
    tconv_all<<<9792, dim3(32, 8)>>>(bw1, cw1, bw2, cw2,
                                     (__half*)w1b, (__half*)w1c,
                                     (__half*)w2b, (__half*)w2c);

    // layer 1: both branches in one launch (z=2), M=2048, N=768
    tgemm_l1<<<dim3(QHD/128, MROWS/128, 2), 256, SMEM_L1>>>(
        (__half*)bxA, (__half*)w1b, bb1, CDIM,   (__half*)h1,
        (__half*)ckA, (__half*)w1c, cb1, 2*CDIM, (__half*)h2);

    // layer 2: both branches (z=2), M=2048 (128/CTA), N=6144 (96/CTA)
    tgemm_l2<<<dim3((VQn*QHD)/96, MROWS/128, 2), 256, SMEM_L2>>>(
        (__half*)h1, (__half*)w2b, bb2,
        (__half*)h2, (__half*)w2c, cb2, out);

    write_mask<<<(NB*OUTROWS + 255)/256, 256>>>(boxqm, clickqm, out + FEAT_ELEMS);
}

// round 14
// speedup vs baseline: 1.2624x; 1.0550x over previous
#include <cuda_runtime.h>
#include <cuda_fp16.h>
#include <math_constants.h>
#include <cstdint>

#define NB 32
#define NPROP 256
#define NCLS 19
#define NPTS 4096
#define NBQ 64
#define NCK 64
#define CDIM 256
#define QHD 768
#define VQn 8
#define MROWS (NB*NBQ)                 // 2048
#define OUTROWS 1024
#define FEAT_ELEMS (NB*OUTROWS*QHD)    // 25165824

// ================= device scratch =================
__device__ int   g_match[MROWS];
__device__ unsigned long long g_nnkey[MROWS*8];   // per-chunk NN keys

__device__ __half g_bxA[MROWS*CDIM];        // [2048,256]
__device__ __half g_ckA[MROWS*2*CDIM];      // [2048,512]
__device__ __half g_w1b[QHD*CDIM];          // [768,256]  (N,K)
__device__ __half g_w1c[QHD*2*CDIM];        // [768,512]
__device__ __half g_w2b[VQn*QHD*QHD];       // [6144,768]
__device__ __half g_w2c[VQn*QHD*QHD];       // [6144,768]
__device__ __half g_h1[MROWS*QHD];          // box hidden fp16
__device__ __half g_h2[MROWS*QHD];          // click hidden fp16

// ================= helpers =================
__device__ __forceinline__ uint32_t smem_u32(const void* p) {
    uint32_t a;
    asm("{ .reg .u64 t; cvta.to.shared.u64 t, %1; cvt.u32.u64 %0, t; }" : "=r"(a) : "l"(p));
    return a;
}
__device__ __forceinline__ void cp16(uint32_t dst, const void* src) {
    asm volatile("cp.async.cg.shared.global [%0], [%1], 16;" :: "r"(dst), "l"(src));
}
#define CP_COMMIT() asm volatile("cp.async.commit_group;" ::: "memory")
#define CP_WAIT1()  asm volatile("cp.async.wait_group 1;" ::: "memory")

__device__ __forceinline__ void ldsm_x4(uint32_t* r, uint32_t addr) {
    asm volatile("ldmatrix.sync.aligned.m8n8.x4.shared.b16 {%0,%1,%2,%3}, [%4];"
        : "=r"(r[0]), "=r"(r[1]), "=r"(r[2]), "=r"(r[3]) : "r"(addr));
}
__device__ __forceinline__ void ldsm_x2(uint32_t* r, uint32_t addr) {
    asm volatile("ldmatrix.sync.aligned.m8n8.x2.shared.b16 {%0,%1}, [%2];"
        : "=r"(r[0]), "=r"(r[1]) : "r"(addr));
}
__device__ __forceinline__ void mma16816(float* d, const uint32_t* a, const uint32_t* b) {
    asm volatile(
        "mma.sync.aligned.m16n8k16.row.col.f32.f16.f16.f32 "
        "{%0,%1,%2,%3}, {%4,%5,%6,%7}, {%8,%9}, {%0,%1,%2,%3};"
        : "+f"(d[0]), "+f"(d[1]), "+f"(d[2]), "+f"(d[3])
        : "r"(a[0]), "r"(a[1]), "r"(a[2]), "r"(a[3]), "r"(b[0]), "r"(b[1]));
}

// ================= prep A: box match (blocks 0..31) + click NN (blocks 32..287) =================
#define NN_PTS 512
__global__ void prep_match_nn(const float* __restrict__ logits,
                              const float* __restrict__ corners,
                              const float* __restrict__ box_query,
                              const float* __restrict__ enc_xyz,
                              const float* __restrict__ click_query) {
    __shared__ float s_buf[NPROP*8];           // 8KB, reused by both segments
    int u = blockIdx.x, t = threadIdx.x;
    if (u < NB) {
        // ---- box_prep_match ----
        float* s_mn  = s_buf;                  // [NPROP*3]
        float* s_mx  = s_buf + NPROP*3;        // [NPROP*3]
        float* s_vol = s_buf + NPROP*6;        // [NPROP]
        float* s_msk = s_buf + NPROP*7;        // [NPROP]
        int b = u;
        {
            int p = b*NPROP + t;
            const float* l = logits + (size_t)p * NCLS;
            float best = l[0]; int bi = 0;
            #pragma unroll
            for (int k = 1; k < NCLS; k++) { float v = l[k]; if (v > best) { best = v; bi = k; } }
            s_msk[t] = (bi != NCLS - 1) ? 1.f : 0.f;
            const float* cr = corners + (size_t)p * 24;
            float mn0 = cr[0], mn1 = cr[1], mn2 = cr[2];
            float mx0 = cr[0], mx1 = cr[1], mx2 = cr[2];
            #pragma unroll
            for (int c = 1; c < 8; c++) {
                float x = cr[c*3+0], y = cr[c*3+1], z = cr[c*3+2];
                mn0 = fminf(mn0, x); mx0 = fmaxf(mx0, x);
                mn1 = fminf(mn1, y); mx1 = fmaxf(mx1, y);
                mn2 = fminf(mn2, z); mx2 = fmaxf(mx2, z);
            }
            s_mn[t*3+0] = mn0; s_mn[t*3+1] = mn1; s_mn[t*3+2] = mn2;
            s_mx[t*3+0] = mx0; s_mx[t*3+1] = mx1; s_mx[t*3+2] = mx2;
            s_vol[t] = (mx0-mn0)*(mx1-mn1)*(mx2-mn2);
        }
        __syncthreads();
        if (t < NBQ) {
            const float* cq = box_query + ((size_t)b*NBQ + t) * 24;
            float mn0 = cq[0], mn1 = cq[1], mn2 = cq[2];
            float mx0 = cq[0], mx1 = cq[1], mx2 = cq[2];
            #pragma unroll
            for (int c = 1; c < 8; c++) {
                float x = cq[c*3+0], y = cq[c*3+1], z = cq[c*3+2];
                mn0 = fminf(mn0, x); mx0 = fmaxf(mx0, x);
                mn1 = fminf(mn1, y); mx1 = fmaxf(mx1, y);
                mn2 = fminf(mn2, z); mx2 = fmaxf(mx2, z);
            }
            float volq = (mx0-mn0)*(mx1-mn1)*(mx2-mn2);
            float best = -1.f; int bi = 0;
            for (int p = 0; p < NPROP; p++) {
                float ix = fmaxf(fminf(mx0, s_mx[p*3+0]) - fmaxf(mn0, s_mn[p*3+0]), 0.f);
                float iy = fmaxf(fminf(mx1, s_mx[p*3+1]) - fmaxf(mn1, s_mn[p*3+1]), 0.f);
                float iz = fmaxf(fminf(mx2, s_mx[p*3+2]) - fmaxf(mn2, s_mn[p*3+2]), 0.f);
                float inter = ix*iy*iz;
                float iou = inter / (volq + s_vol[p] - inter + 1e-8f) * s_msk[p];
                if (iou > best) { best = iou; bi = p; }
            }
            g_match[b*NBQ + t] = bi;
        }
    } else {
        // ---- click_nn ----
        float* s_xyz = s_buf;                  // NN_PTS*3 = 6KB
        int v = u - NB;
        int b = v >> 3, ck = v & 7;
        const float* src = enc_xyz + ((size_t)b*NPTS + ck*NN_PTS) * 3;
        for (int i = t; i < NN_PTS*3; i += 256) s_xyz[i] = src[i];
        __syncthreads();
        int warp = t >> 5, lane = t & 31;
        for (int q = warp; q < NCK; q += 8) {
            const float* cq = click_query + ((size_t)b*NCK + q) * 3;
            float cx = cq[0], cy = cq[1], cz = cq[2];
            float best = CUDART_INF_F; int bi = 0;
            for (int p = lane; p < NN_PTS; p += 32) {
                float dx = cx - s_xyz[p*3+0];
                float dy = cy - s_xyz[p*3+1];
                float dz = cz - s_xyz[p*3+2];
                float d = dx*dx + dy*dy + dz*dz;
                if (d < best) { best = d; bi = p; }
            }
            #pragma unroll
            for (int off = 16; off; off >>= 1) {
                float ob = __shfl_xor_sync(0xffffffffu, best, off);
                int   oi = __shfl_xor_sync(0xffffffffu, bi, off);
                if (ob < best || (ob == best && oi < bi)) { best = ob; bi = oi; }
            }
            if (lane == 0)
                g_nnkey[(b*NCK + q)*8 + ck] =
                    ((unsigned long long)__float_as_uint(best) << 32)
                    | (unsigned)(ck*NN_PTS + bi);
        }
    }
}

// ================= prep B: gather (blocks 0..255) + click build (blocks 256..1279) =================
__global__ void prep_gather_build(const float* __restrict__ prop_features,
                                  const float* __restrict__ enc_features,
                                  const float* __restrict__ click_query,
                                  const float* __restrict__ pc_min,
                                  const float* __restrict__ pc_max,
                                  const float* __restrict__ gauss) {
    int u = blockIdx.x, t = threadIdx.x;
    if (u < 256) {
        // gather_box: warp per row, 8 rows per block
        int warp = u * 8 + (t >> 5);
        int lane = t & 31;
        int b = warp >> 6;
        int m = g_match[warp];
        const float4* src = (const float4*)(prop_features + ((size_t)b*NPROP + m) * CDIM);
        __half* dst = g_bxA + (size_t)warp * CDIM;
        #pragma unroll
        for (int i = 0; i < 2; i++) {
            float4 v = src[lane + i*32];
            int o = (lane + i*32) * 4;
            dst[o+0] = __float2half_rn(v.x);
            dst[o+1] = __float2half_rn(v.y);
            dst[o+2] = __float2half_rn(v.z);
            dst[o+3] = __float2half_rn(v.w);
        }
    } else {
        // click_build: 2 rows per block (128 threads each)
        int r = (u - 256) * 2 + (t >> 7);
        int tt = t & 127;
        int b = r >> 6;
        unsigned long long key = ~0ull;
        #pragma unroll
        for (int ck = 0; ck < 8; ck++) {
            unsigned long long k = g_nnkey[r*8 + ck];
            if (k < key) key = k;
        }
        int nn = (int)(key & 0xffffffffull);
        const float2* src = (const float2*)(enc_features + ((size_t)b*NPTS + nn) * CDIM);
        float2 v = src[tt];
        int o = r*2*CDIM + 2*tt;
        g_ckA[o+0] = __float2half_rn(v.x);
        g_ckA[o+1] = __float2half_rn(v.y);
        const float* cq = click_query + (size_t)r * 3;
        float pr = 0.f;
        #pragma unroll
        for (int d = 0; d < 3; d++) {
            float x01 = (cq[d] - pc_min[b*3+d]) / (pc_max[b*3+d] - pc_min[b*3+d]);
            pr += x01 * 6.283185307179586f * gauss[d*(CDIM/2) + tt];
        }
        g_ckA[r*2*CDIM + CDIM + tt]       = __float2half_rn(sinf(pr));
        g_ckA[r*2*CDIM + CDIM + 128 + tt] = __float2half_rn(cosf(pr));
    }
}

// ================= prep C: weight transpose-convert + mask =================
// [0,192) w1b, [192,576) w1c, [576,5184) w2b, [5184,9792) w2c, [9792,9920) mask
__global__ void tconv_all(const float* __restrict__ bw1, const float* __restrict__ cw1,
                          const float* __restrict__ bw2, const float* __restrict__ cw2,
                          __half* __restrict__ dw1b, __half* __restrict__ dw1c,
                          __half* __restrict__ dw2b, __half* __restrict__ dw2c,
                          const float* __restrict__ box_qmask,
                          const float* __restrict__ click_qmask,
                          float* __restrict__ out_mask) {
    int u = blockIdx.x;
    int tx = threadIdx.x, ty = threadIdx.y;
    if (u >= 9792) {
        int i = (u - 9792) * 256 + ty * 32 + tx;
        int b = i >> 10, r = i & 1023;
        out_mask[i] = (r < NBQ*VQn) ? box_qmask[b*NBQ + (r >> 3)]
                                    : click_qmask[b*NCK + ((r - NBQ*VQn) >> 3)];
        return;
    }
    __shared__ float tile[32][33];
    const float* src; __half* dst; int K, N, nx;
    if      (u < 192)  { src = bw1; dst = dw1b; K = CDIM;   N = QHD;     nx = 24;  }
    else if (u < 576)  { src = cw1; dst = dw1c; K = 2*CDIM; N = QHD;     nx = 24;  u -= 192; }
    else if (u < 5184) { src = bw2; dst = dw2b; K = QHD;    N = VQn*QHD; nx = 192; u -= 576; }
    else               { src = cw2; dst = dw2c; K = QHD;    N = VQn*QHD; nx = 192; u -= 5184; }
    int n0 = (u % nx) * 32, k0 = (u / nx) * 32;
    #pragma unroll
    for (int j = 0; j < 4; j++)
        tile[ty + 8*j][tx] = src[(size_t)(k0 + ty + 8*j) * N + n0 + tx];
    __syncthreads();
    #pragma unroll
    for (int j = 0; j < 4; j++)
        dst[(size_t)(n0 + ty + 8*j) * K + k0 + tx] = __float2half_rn(tile[tx][ty + 8*j]);
}

// ================= GEMMs =================
#define NSTAGE 3
#define ROWB2 144

// ---- layer 1: 128x128 CTA tile, BK=64, warp 64x32, 3-stage, occ 2 ----
#define L1_AT (128*ROWB2)                 // 18432
#define L1_STAGE (2*L1_AT)                // 36864
#define SMEM_L1 (NSTAGE*L1_STAGE + 512)   // 111104

__global__ __launch_bounds__(256, 2) void tgemm_l1(
        const __half* A0, const __half* B0, const float* b0, int K0, __half* H0,
        const __half* A1, const __half* B1, const float* b1, int K1, __half* H1) {
    extern __shared__ __align__(16) char smem_raw[];
    const uint32_t base = smem_u32(smem_raw);
    float* s_bias = (float*)(smem_raw + NSTAGE * L1_STAGE);
    int z = blockIdx.z, t = threadIdx.x;
    const __half* A = z ? A1 : A0;
    const __half* B = z ? B1 : B0;
    const float* bias = z ? b1 : b0;
    int K = z ? K1 : K0;
    __half* H = z ? H1 : H0;
    int m0 = blockIdx.y * 128, n0 = blockIdx.x * 128;
    if (t < 128) s_bias[t] = bias[n0 + t];

    const int lid = t & 31;
    const int mwarp = (t >> 5) & 1, nwarp = t >> 6;

    float acc[4][4][4];
    #pragma unroll
    for (int mi = 0; mi < 4; mi++)
        #pragma unroll
        for (int ni = 0; ni < 4; ni++)
            #pragma unroll
            for (int r = 0; r < 4; r++) acc[mi][ni][r] = 0.f;

    auto load_slab = [&](int s) {
        uint32_t sb = base + (s % NSTAGE) * L1_STAGE;
        size_t kof = (size_t)s * 64;
        #pragma unroll
        for (int i = 0; i < 4; i++) {          // A: 128 rows x 8 chunks
            int c = i * 256 + t;
            int row = c >> 3, chk = c & 7;
            cp16(sb + row * ROWB2 + chk * 16,
                 A + (size_t)(m0 + row) * K + kof + chk * 8);
        }
        #pragma unroll
        for (int i = 0; i < 4; i++) {          // B: 128 rows x 8 chunks
            int c = i * 256 + t;
            int row = c >> 3, chk = c & 7;
            cp16(sb + L1_AT + row * ROWB2 + chk * 16,
                 B + (size_t)(n0 + row) * K + kof + chk * 8);
        }
    };
    auto compute_stage = [&](int s) {
        uint32_t sb = base + (s % NSTAGE) * L1_STAGE;
        uint32_t aP = sb, bP = sb + L1_AT;
        #pragma unroll
        for (int ks = 0; ks < 64; ks += 16) {
            uint32_t ah[4][4], bh[4][2];
            uint32_t aoff = (uint32_t)((mwarp*64 + (lid & 15)) * ROWB2
                                       + (ks + ((lid >> 4) << 3)) * 2);
            #pragma unroll
            for (int mi = 0; mi < 4; mi++)
                ldsm_x4(ah[mi], aP + aoff + mi*16*ROWB2);
            uint32_t boff = (uint32_t)((nwarp*32 + (lid & 7)) * ROWB2
                                       + (ks + (((lid >> 3) & 1) << 3)) * 2);
            #pragma unroll
            for (int ni = 0; ni < 4; ni++)
                ldsm_x2(bh[ni], bP + boff + ni*8*ROWB2);
            #pragma unroll
            for (int mi = 0; mi < 4; mi++)
                #pragma unroll
                for (int ni = 0; ni < 4; ni++)
                    mma16816(acc[mi][ni], ah[mi], bh[ni]);
        }
    };

    const int S = K >> 6;                      // 4 or 8 slabs
    load_slab(0); CP_COMMIT();
    if (S > 1) load_slab(1);
    CP_COMMIT();
    for (int s = 0; s < S; s++) {
        CP_WAIT1();
        __syncthreads();
        if (s + 2 < S) load_slab(s + 2);
        CP_COMMIT();
        compute_stage(s);
    }

    const int mb = m0 + mwarp * 64;
    const int nb = n0 + nwarp * 32;
    #pragma unroll
    for (int mi = 0; mi < 4; mi++) {
        int r0 = mb + mi*16 + (lid >> 2);
        #pragma unroll
        for (int ni = 0; ni < 4; ni++) {
            int n = nb + ni*8 + (lid & 3)*2;
            float v00 = fmaxf(acc[mi][ni][0] + s_bias[n   - n0], 0.f);
            float v01 = fmaxf(acc[mi][ni][1] + s_bias[n+1 - n0], 0.f);
            float v10 = fmaxf(acc[mi][ni][2] + s_bias[n   - n0], 0.f);
            float v11 = fmaxf(acc[mi][ni][3] + s_bias[n+1 - n0], 0.f);
            size_t o0 = (size_t)r0 * QHD + n;
            size_t o1 = (size_t)(r0 + 8) * QHD + n;
            H[o0]   = __float2half_rn(v00);
            H[o0+1] = __float2half_rn(v01);
            H[o1]   = __float2half_rn(v10);
            H[o1+1] = __float2half_rn(v11);
        }
    }
}

// ---- layer 2: 128x96 tile, BK=64, warp 64x24, 3-stage, occ 2 (proven R11) ----
#define L2_AT (128*ROWB2)              // 18432
#define L2_BT (96*ROWB2)               // 13824
#define L2_STAGE (L2_AT + L2_BT)       // 32256
#define SMEM_L2 (NSTAGE*L2_STAGE + 512) // 97280

__global__ __launch_bounds__(256, 2) void tgemm_l2(
        const __half* A0, const __half* B0, const float* b0,
        const __half* A1, const __half* B1, const float* b1,
        float* __restrict__ outf) {
    extern __shared__ __align__(16) char smem_raw[];
    const uint32_t base = smem_u32(smem_raw);
    float* s_bias = (float*)(smem_raw + NSTAGE * L2_STAGE);
    int z = blockIdx.z, t = threadIdx.x;
    const __half* A = z ? A1 : A0;
    const __half* B = z ? B1 : B0;
    const float* bias = z ? b1 : b0;
    const int K = QHD;
    int m0 = blockIdx.y * 128, n0 = blockIdx.x * 96;
    if (t < 96) s_bias[t] = bias[n0 + t];

    const int lid = t & 31;
    const int mwarp = (t >> 5) & 1, nwarp = t >> 6;

    float acc[4][3][4];
    #pragma unroll
    for (int mi = 0; mi < 4; mi++)
        #pragma unroll
        for (int ni = 0; ni < 3; ni++)
            #pragma unroll
            for (int r = 0; r < 4; r++) acc[mi][ni][r] = 0.f;

    auto load_slab = [&](int s) {
        uint32_t sb = base + (s % NSTAGE) * L2_STAGE;
        size_t kof = (size_t)s * 64;
        #pragma unroll
        for (int i = 0; i < 4; i++) {
            int c = i * 256 + t;
            int row = c >> 3, chk = c & 7;
            cp16(sb + row * ROWB2 + chk * 16,
                 A + (size_t)(m0 + row) * K + kof + chk * 8);
        }
        #pragma unroll
        for (int i = 0; i < 3; i++) {
            int c = i * 256 + t;
            int row = c >> 3, chk = c & 7;
            cp16(sb + L2_AT + row * ROWB2 + chk * 16,
                 B + (size_t)(n0 + row) * K + kof + chk * 8);
        }
    };
    auto compute_stage = [&](int s) {
        uint32_t sb = base + (s % NSTAGE) * L2_STAGE;
        uint32_t aP = sb, bP = sb + L2_AT;
        #pragma unroll
        for (int ks = 0; ks < 64; ks += 16) {
            uint32_t ah[4][4], bh[3][2];
            uint32_t aoff = (uint32_t)((mwarp*64 + (lid & 15)) * ROWB2
                                       + (ks + ((lid >> 4) << 3)) * 2);
            #pragma unroll
            for (int mi = 0; mi < 4; mi++)
                ldsm_x4(ah[mi], aP + aoff + mi*16*ROWB2);
            uint32_t boff = (uint32_t)((nwarp*24 + (lid & 7)) * ROWB2
                                       + (ks + (((lid >> 3) & 1) << 3)) * 2);
            #pragma unroll
            for (int ni = 0; ni < 3; ni++)
                ldsm_x2(bh[ni], bP + boff + ni*8*ROWB2);
            #pragma unroll
            for (int mi = 0; mi < 4; mi++)
                #pragma unroll
                for (int ni = 0; ni < 3; ni++)
                    mma16816(acc[mi][ni], ah[mi], bh[ni]);
        }
    };

    const int S = K >> 6;                      // 12 slabs
    load_slab(0); CP_COMMIT();
    load_slab(1); CP_COMMIT();
    for (int s = 0; s < S; s++) {
        CP_WAIT1();
        __syncthreads();
        if (s + 2 < S) load_slab(s + 2);
        CP_COMMIT();
        compute_stage(s);
    }

    const int mb = m0 + mwarp * 64;
    const int nb = n0 + nwarp * 24;
    const int boff = z ? (NBQ * VQn) : 0;
    #pragma unroll
    for (int mi = 0; mi < 4; mi++) {
        int r0 = mb + mi*16 + (lid >> 2);
        #pragma unroll
        for (int ni = 0; ni < 3; ni++) {
            int n = nb + ni*8 + (lid & 3)*2;
            float v00 = acc[mi][ni][0] + s_bias[n   - n0];
            float v01 = acc[mi][ni][1] + s_bias[n+1 - n0];
            float v10 = acc[mi][ni][2] + s_bias[n   - n0];
            float v11 = acc[mi][ni][3] + s_bias[n+1 - n0];
            int vq = n / QHD, h = n - vq * QHD;
            int b0i = r0 >> 6, q0 = r0 & 63;
            int r1 = r0 + 8;
            int b1i = r1 >> 6, q1 = r1 & 63;
            size_t o0 = ((size_t)(b0i*OUTROWS + boff + q0*VQn + vq)) * QHD + h;
            size_t o1 = ((size_t)(b1i*OUTROWS + boff + q1*VQn + vq)) * QHD + h;
            outf[o0]   = v00; outf[o0+1] = v01;
            outf[o1]   = v10; outf[o1+1] = v11;
        }
    }
}

// ================= host =================
extern "C" void kernel_launch(void* const* d_in, const int* in_sizes, int n_in,
                              void* d_out, int out_size) {
    const float* sem     = (const float*)d_in[0];
    const float* propf   = (const float*)d_in[1];
    const float* boxc    = (const float*)d_in[2];
    const float* encxyz  = (const float*)d_in[3];
    const float* encf    = (const float*)d_in[4];
    const float* pcmin   = (const float*)d_in[5];
    const float* pcmax   = (const float*)d_in[6];
    const float* boxq    = (const float*)d_in[7];
    const float* boxqm   = (const float*)d_in[8];
    const float* clickq  = (const float*)d_in[9];
    const float* clickqm = (const float*)d_in[10];
    const float* gauss   = (const float*)d_in[11];
    const float* bw1     = (const float*)d_in[12];
    const float* bb1     = (const float*)d_in[13];
    const float* bw2     = (const float*)d_in[14];
    const float* bb2     = (const float*)d_in[15];
    const float* cw1     = (const float*)d_in[16];
    const float* cb1     = (const float*)d_in[17];
    const float* cw2     = (const float*)d_in[18];
    const float* cb2     = (const float*)d_in[19];
    float* out = (float*)d_out;

    void *bxA, *ckA, *w1b, *w1c, *w2b, *w2c, *h1, *h2;
    cudaGetSymbolAddress(&bxA, g_bxA); cudaGetSymbolAddress(&ckA, g_ckA);
    cudaGetSymbolAddress(&w1b, g_w1b); cudaGetSymbolAddress(&w1c, g_w1c);
    cudaGetSymbolAddress(&w2b, g_w2b); cudaGetSymbolAddress(&w2c, g_w2c);
    cudaGetSymbolAddress(&h1,  g_h1);  cudaGetSymbolAddress(&h2,  g_h2);

    cudaFuncSetAttribute(tgemm_l1, cudaFuncAttributeMaxDynamicSharedMemorySize, SMEM_L1);
    cudaFuncSetAttribute(tgemm_l2, cudaFuncAttributeMaxDynamicSharedMemorySize, SMEM_L2);

    prep_match_nn<<<NB + NB*(NPTS/NN_PTS), 256>>>(sem, boxc, boxq, encxyz, clickq);
    prep_gather_build<<<256 + MROWS/2, 256>>>(propf, encf, clickq, pcmin, pcmax, gauss);
    tconv_all<<<9920, dim3(32, 8)>>>(bw1, cw1, bw2, cw2,
                                     (__half*)w1b, (__half*)w1c,
                                     (__half*)w2b, (__half*)w2c,
                                     boxqm, clickqm, out + FEAT_ELEMS);

    // layer 1: both branches (z=2), M=2048, N=768
    tgemm_l1<<<dim3(QHD/128, MROWS/128, 2), 256, SMEM_L1>>>(
        (__half*)bxA, (__half*)w1b, bb1, CDIM,   (__half*)h1,
        (__half*)ckA, (__half*)w1c, cb1, 2*CDIM, (__half*)h2);

    // layer 2: both branches (z=2), M=2048 (128/CTA), N=6144 (96/CTA)
    tgemm_l2<<<dim3((VQn*QHD)/96, MROWS/128, 2), 256, SMEM_L2>>>(
        (__half*)h1, (__half*)w2b, bb2,
        (__half*)h2, (__half*)w2c, cb2, out);
}

// round 17
// speedup vs baseline: 1.3013x; 1.0308x over previous
#include <cuda_runtime.h>
#include <cuda_fp16.h>
#include <math_constants.h>
#include <cstdint>

#define NB 32
#define NPROP 256
#define NCLS 19
#define NPTS 4096
#define NBQ 64
#define NCK 64
#define CDIM 256
#define QHD 768
#define VQn 8
#define MROWS (NB*NBQ)                 // 2048
#define OUTROWS 1024
#define FEAT_ELEMS (NB*OUTROWS*QHD)    // 25165824

// ================= device scratch =================
__device__ int   g_match[MROWS];
__device__ unsigned long long g_nnkey[MROWS*8];

__device__ __half g_bxA[MROWS*CDIM];        // [2048,256]  (M,K)
__device__ __half g_ckA[MROWS*2*CDIM];      // [2048,512]
__device__ __half g_w1b[CDIM*QHD];          // [256,768]   (K,N) fp16
__device__ __half g_w1c[2*CDIM*QHD];        // [512,768]
__device__ __half g_w2b[QHD*VQn*QHD];       // [768,6144]
__device__ __half g_w2c[QHD*VQn*QHD];       // [768,6144]
__device__ __half g_h1[MROWS*QHD];          // box hidden fp16
__device__ __half g_h2[MROWS*QHD];          // click hidden fp16

// ================= helpers =================
__device__ __forceinline__ uint32_t smem_u32(const void* p) {
    uint32_t a;
    asm("{ .reg .u64 t; cvta.to.shared.u64 t, %1; cvt.u32.u64 %0, t; }" : "=r"(a) : "l"(p));
    return a;
}
__device__ __forceinline__ void cp16(uint32_t dst, const void* src) {
    asm volatile("cp.async.cg.shared.global [%0], [%1], 16;" :: "r"(dst), "l"(src));
}
#define CP_COMMIT() asm volatile("cp.async.commit_group;" ::: "memory")
#define CP_WAIT1()  asm volatile("cp.async.wait_group 1;" ::: "memory")

__device__ __forceinline__ void ldsm_x4(uint32_t* r, uint32_t addr) {
    asm volatile("ldmatrix.sync.aligned.m8n8.x4.shared.b16 {%0,%1,%2,%3}, [%4];"
        : "=r"(r[0]), "=r"(r[1]), "=r"(r[2]), "=r"(r[3]) : "r"(addr));
}
// trans: for K-major B storage, yields the row.col b-fragment directly
__device__ __forceinline__ void ldsm_x2t(uint32_t* r, uint32_t addr) {
    asm volatile("ldmatrix.sync.aligned.m8n8.x2.trans.shared.b16 {%0,%1}, [%2];"
        : "=r"(r[0]), "=r"(r[1]) : "r"(addr));
}
__device__ __forceinline__ void mma16816(float* d, const uint32_t* a, const uint32_t* b) {
    asm volatile(
        "mma.sync.aligned.m16n8k16.row.col.f32.f16.f16.f32 "
        "{%0,%1,%2,%3}, {%4,%5,%6,%7}, {%8,%9}, {%0,%1,%2,%3};"
        : "+f"(d[0]), "+f"(d[1]), "+f"(d[2]), "+f"(d[3])
        : "r"(a[0]), "r"(a[1]), "r"(a[2]), "r"(a[3]), "r"(b[0]), "r"(b[1]));
}

// ================= prep A: box match (blocks 0..31) + click NN (blocks 32..287) =================
#define NN_PTS 512
__global__ void prep_match_nn(const float* __restrict__ logits,
                              const float* __restrict__ corners,
                              const float* __restrict__ box_query,
                              const float* __restrict__ enc_xyz,
                              const float* __restrict__ click_query) {
    __shared__ float s_buf[NPROP*8];
    int u = blockIdx.x, t = threadIdx.x;
    if (u < NB) {
        float* s_mn  = s_buf;
        float* s_mx  = s_buf + NPROP*3;
        float* s_vol = s_buf + NPROP*6;
        float* s_msk = s_buf + NPROP*7;
        int b = u;
        {
            int p = b*NPROP + t;
            const float* l = logits + (size_t)p * NCLS;
            float best = l[0]; int bi = 0;
            #pragma unroll
            for (int k = 1; k < NCLS; k++) { float v = l[k]; if (v > best) { best = v; bi = k; } }
            s_msk[t] = (bi != NCLS - 1) ? 1.f : 0.f;
            const float* cr = corners + (size_t)p * 24;
            float mn0 = cr[0], mn1 = cr[1], mn2 = cr[2];
            float mx0 = cr[0], mx1 = cr[1], mx2 = cr[2];
            #pragma unroll
            for (int c = 1; c < 8; c++) {
                float x = cr[c*3+0], y = cr[c*3+1], z = cr[c*3+2];
                mn0 = fminf(mn0, x); mx0 = fmaxf(mx0, x);
                mn1 = fminf(mn1, y); mx1 = fmaxf(mx1, y);
                mn2 = fminf(mn2, z); mx2 = fmaxf(mx2, z);
            }
            s_mn[t*3+0] = mn0; s_mn[t*3+1] = mn1; s_mn[t*3+2] = mn2;
            s_mx[t*3+0] = mx0; s_mx[t*3+1] = mx1; s_mx[t*3+2] = mx2;
            s_vol[t] = (mx0-mn0)*(mx1-mn1)*(mx2-mn2);
        }
        __syncthreads();
        if (t < NBQ) {
            const float* cq = box_query + ((size_t)b*NBQ + t) * 24;
            float mn0 = cq[0], mn1 = cq[1], mn2 = cq[2];
            float mx0 = cq[0], mx1 = cq[1], mx2 = cq[2];
            #pragma unroll
            for (int c = 1; c < 8; c++) {
                float x = cq[c*3+0], y = cq[c*3+1], z = cq[c*3+2];
                mn0 = fminf(mn0, x); mx0 = fmaxf(mx0, x);
                mn1 = fminf(mn1, y); mx1 = fmaxf(mx1, y);
                mn2 = fminf(mn2, z); mx2 = fmaxf(mx2, z);
            }
            float volq = (mx0-mn0)*(mx1-mn1)*(mx2-mn2);
            float best = -1.f; int bi = 0;
            for (int p = 0; p < NPROP; p++) {
                float ix = fmaxf(fminf(mx0, s_mx[p*3+0]) - fmaxf(mn0, s_mn[p*3+0]), 0.f);
                float iy = fmaxf(fminf(mx1, s_mx[p*3+1]) - fmaxf(mn1, s_mn[p*3+1]), 0.f);
                float iz = fmaxf(fminf(mx2, s_mx[p*3+2]) - fmaxf(mn2, s_mn[p*3+2]), 0.f);
                float inter = ix*iy*iz;
                float iou = inter / (volq + s_vol[p] - inter + 1e-8f) * s_msk[p];
                if (iou > best) { best = iou; bi = p; }
            }
            g_match[b*NBQ + t] = bi;
        }
    } else {
        float* s_xyz = s_buf;
        int v = u - NB;
        int b = v >> 3, ck = v & 7;
        const float* src = enc_xyz + ((size_t)b*NPTS + ck*NN_PTS) * 3;
        for (int i = t; i < NN_PTS*3; i += 256) s_xyz[i] = src[i];
        __syncthreads();
        int warp = t >> 5, lane = t & 31;
        for (int q = warp; q < NCK; q += 8) {
            const float* cq = click_query + ((size_t)b*NCK + q) * 3;
            float cx = cq[0], cy = cq[1], cz = cq[2];
            float best = CUDART_INF_F; int bi = 0;
            for (int p = lane; p < NN_PTS; p += 32) {
                float dx = cx - s_xyz[p*3+0];
                float dy = cy - s_xyz[p*3+1];
                float dz = cz - s_xyz[p*3+2];
                float d = dx*dx + dy*dy + dz*dz;
                if (d < best) { best = d; bi = p; }
            }
            #pragma unroll
            for (int off = 16; off; off >>= 1) {
                float ob = __shfl_xor_sync(0xffffffffu, best, off);
                int   oi = __shfl_xor_sync(0xffffffffu, bi, off);
                if (ob < best || (ob == best && oi < bi)) { best = ob; bi = oi; }
            }
            if (lane == 0)
                g_nnkey[(b*NCK + q)*8 + ck] =
                    ((unsigned long long)__float_as_uint(best) << 32)
                    | (unsigned)(ck*NN_PTS + bi);
        }
    }
}

// ================= prep B: gather (0..255) + click build (256..1279) =================
__global__ void prep_gather_build(const float* __restrict__ prop_features,
                                  const float* __restrict__ enc_features,
                                  const float* __restrict__ click_query,
                                  const float* __restrict__ pc_min,
                                  const float* __restrict__ pc_max,
                                  const float* __restrict__ gauss) {
    int u = blockIdx.x, t = threadIdx.x;
    if (u < 256) {
        int warp = u * 8 + (t >> 5);
        int lane = t & 31;
        int b = warp >> 6;
        int m = g_match[warp];
        const float4* src = (const float4*)(prop_features + ((size_t)b*NPROP + m) * CDIM);
        __half* dst = g_bxA + (size_t)warp * CDIM;
        #pragma unroll
        for (int i = 0; i < 2; i++) {
            float4 v = src[lane + i*32];
            int o = (lane + i*32) * 4;
            dst[o+0] = __float2half_rn(v.x);
            dst[o+1] = __float2half_rn(v.y);
            dst[o+2] = __float2half_rn(v.z);
            dst[o+3] = __float2half_rn(v.w);
        }
    } else {
        int r = (u - 256) * 2 + (t >> 7);
        int tt = t & 127;
        int b = r >> 6;
        unsigned long long key = ~0ull;
        #pragma unroll
        for (int ck = 0; ck < 8; ck++) {
            unsigned long long k = g_nnkey[r*8 + ck];
            if (k < key) key = k;
        }
        int nn = (int)(key & 0xffffffffull);
        const float2* src = (const float2*)(enc_features + ((size_t)b*NPTS + nn) * CDIM);
        float2 v = src[tt];
        int o = r*2*CDIM + 2*tt;
        g_ckA[o+0] = __float2half_rn(v.x);
        g_ckA[o+1] = __float2half_rn(v.y);
        const float* cq = click_query + (size_t)r * 3;
        float pr = 0.f;
        #pragma unroll
        for (int d = 0; d < 3; d++) {
            float x01 = (cq[d] - pc_min[b*3+d]) / (pc_max[b*3+d] - pc_min[b*3+d]);
            pr += x01 * 6.283185307179586f * gauss[d*(CDIM/2) + tt];
        }
        g_ckA[r*2*CDIM + CDIM + tt]       = __float2half_rn(sinf(pr));
        g_ckA[r*2*CDIM + CDIM + 128 + tt] = __float2half_rn(cosf(pr));
    }
}

// ================= prep C: streaming f32->fp16 weight convert (no transpose) + mask =================
#define Q1 (CDIM*QHD/4)            // 49152
#define Q2 (2*CDIM*QHD/4)          // 98304
#define Q3 (QHD*VQn*QHD/4)         // 1179648
#define QM (NB*OUTROWS/4)          // 8192
#define QTOT (Q1+Q2+2*Q3+QM)       // 2514944

__global__ void conv_all(const float* __restrict__ bw1, const float* __restrict__ cw1,
                         const float* __restrict__ bw2, const float* __restrict__ cw2,
                         const float* __restrict__ box_qmask,
                         const float* __restrict__ click_qmask,
                         float* __restrict__ out_mask) {
    for (int q = blockIdx.x * blockDim.x + threadIdx.x; q < QTOT;
         q += gridDim.x * blockDim.x) {
        if (q < Q1 + Q2 + 2*Q3) {
            const float* src; __half* dst; int local;
            if      (q < Q1)          { src = bw1; dst = g_w1b; local = q; }
            else if (q < Q1+Q2)       { src = cw1; dst = g_w1c; local = q - Q1; }
            else if (q < Q1+Q2+Q3)    { src = bw2; dst = g_w2b; local = q - Q1 - Q2; }
            else                      { src = cw2; dst = g_w2c; local = q - Q1 - Q2 - Q3; }
            float4 v = ((const float4*)src)[local];
            ((__half2*)dst)[local*2]   = __floats2half2_rn(v.x, v.y);
            ((__half2*)dst)[local*2+1] = __floats2half2_rn(v.z, v.w);
        } else {
            int i0 = (q - (Q1 + Q2 + 2*Q3)) * 4;
            #pragma unroll
            for (int j = 0; j < 4; j++) {
                int i = i0 + j;
                int b = i >> 10, r = i & 1023;
                out_mask[i] = (r < NBQ*VQn) ? box_qmask[b*NBQ + (r >> 3)]
                                            : click_qmask[b*NCK + ((r - NBQ*VQn) >> 3)];
            }
        }
    }
}

// ================= unified GEMM body: 128x96 tile, BK=64, warp 64x24, 3-stage =================
// A [M,K] fp16 row-major; B [K,N] fp16 row-major (trans ldmatrix).
#define NSTAGE 3
#define ROWA 144                        // A row: 64 fp16 = 128B + 16 pad (9 mod 8 = 1)
#define ROWBK 208                       // B row: 96 fp16 = 192B + 16 pad (13 mod 8 = 5)
#define G_AT (128*ROWA)                 // 18432
#define G_BT (64*ROWBK)                 // 13312
#define G_STAGE (G_AT + G_BT)           // 31744
#define SMEM_G (NSTAGE*G_STAGE + 512)   // 95744

__device__ __forceinline__ void gemm_body96(
        const __half* __restrict__ A, const __half* __restrict__ B,
        int K, int Nw, int m0, int n0, uint32_t base, int t, float acc[4][3][4]) {
    const int lid = t & 31;
    const int mwarp = (t >> 5) & 1, nwarp = t >> 6;
    const int S = K >> 6;

    auto load_slab = [&](int s) {
        uint32_t sb = base + (s % NSTAGE) * G_STAGE;
        size_t kof = (size_t)s * 64;
        #pragma unroll
        for (int i = 0; i < 4; i++) {          // A: 128 rows x 8 chunks
            int c = i * 256 + t;
            int row = c >> 3, chk = c & 7;
            cp16(sb + row * ROWA + chk * 16,
                 A + (size_t)(m0 + row) * K + kof + chk * 8);
        }
        #pragma unroll
        for (int i = 0; i < 3; i++) {          // B: 64 k-rows x 12 chunks (192B each)
            int c = i * 256 + t;
            int row = c >> 4 ;                 // 768 tasks: row = c/12? use 12-chunk rows
            // recompute with 12 chunks per row:
            row = c / 12; int chk = c - row * 12;
            cp16(sb + G_AT + row * ROWBK + chk * 16,
                 B + (size_t)(kof + row) * Nw + n0 + chk * 8);
        }
    };
    auto compute_stage = [&](int s) {
        uint32_t sb = base + (s % NSTAGE) * G_STAGE;
        uint32_t aP = sb, bP = sb + G_AT;
        #pragma unroll
        for (int ks = 0; ks < 64; ks += 16) {
            uint32_t ah[4][4], bh[3][2];
            uint32_t aoff = (uint32_t)((mwarp*64 + (lid & 15)) * ROWA
                                       + (ks + ((lid >> 4) << 3)) * 2);
            #pragma unroll
            for (int mi = 0; mi < 4; mi++)
                ldsm_x4(ah[mi], aP + aoff + mi*16*ROWA);
            uint32_t brow = bP + (uint32_t)(ks + (lid & 15)) * ROWBK;
            #pragma unroll
            for (int ni = 0; ni < 3; ni++)
                ldsm_x2t(bh[ni], brow + (nwarp*24 + ni*8) * 2);
            #pragma unroll
            for (int mi = 0; mi < 4; mi++)
                #pragma unroll
                for (int ni = 0; ni < 3; ni++)
                    mma16816(acc[mi][ni], ah[mi], bh[ni]);
        }
    };

    load_slab(0); CP_COMMIT();
    if (S > 1) load_slab(1);
    CP_COMMIT();
    for (int s = 0; s < S; s++) {
        CP_WAIT1();
        __syncthreads();
        if (s + 2 < S) load_slab(s + 2);
        CP_COMMIT();
        compute_stage(s);
    }
}

// layer 1: relu(D+bias) -> fp16 hidden. grid (768/96=8, 16, 2) = 256 CTAs
__global__ __launch_bounds__(256, 2) void tgemm_l1(
        const __half* A0, const __half* B0, const float* b0, int K0, __half* H0,
        const __half* A1, const __half* B1, const float* b1, int K1, __half* H1) {
    extern __shared__ __align__(16) char smem_raw[];
    const uint32_t base = smem_u32(smem_raw);
    float* s_bias = (float*)(smem_raw + NSTAGE * G_STAGE);
    int z = blockIdx.z, t = threadIdx.x;
    const __half* A = z ? A1 : A0;
    const __half* B = z ? B1 : B0;
    const float* bias = z ? b1 : b0;
    int K = z ? K1 : K0;
    __half* H = z ? H1 : H0;
    int m0 = blockIdx.y * 128, n0 = blockIdx.x * 96;
    if (t < 96) s_bias[t] = bias[n0 + t];

    const int lid = t & 31;
    const int mwarp = (t >> 5) & 1, nwarp = t >> 6;

    float acc[4][3][4];
    #pragma unroll
    for (int mi = 0; mi < 4; mi++)
        #pragma unroll
        for (int ni = 0; ni < 3; ni++)
            #pragma unroll
            for (int r = 0; r < 4; r++) acc[mi][ni][r] = 0.f;

    gemm_body96(A, B, K, QHD, m0, n0, base, t, acc);

    const int mb = m0 + mwarp * 64;
    const int nb = n0 + nwarp * 24;
    #pragma unroll
    for (int mi = 0; mi < 4; mi++) {
        int r0 = mb + mi*16 + (lid >> 2);
        #pragma unroll
        for (int ni = 0; ni < 3; ni++) {
            int n = nb + ni*8 + (lid & 3)*2;
            float v00 = fmaxf(acc[mi][ni][0] + s_bias[n   - n0], 0.f);
            float v01 = fmaxf(acc[mi][ni][1] + s_bias[n+1 - n0], 0.f);
            float v10 = fmaxf(acc[mi][ni][2] + s_bias[n   - n0], 0.f);
            float v11 = fmaxf(acc[mi][ni][3] + s_bias[n+1 - n0], 0.f);
            size_t o0 = (size_t)r0 * QHD + n;
            size_t o1 = (size_t)(r0 + 8) * QHD + n;
            H[o0]   = __float2half_rn(v00);
            H[o0+1] = __float2half_rn(v01);
            H[o1]   = __float2half_rn(v10);
            H[o1+1] = __float2half_rn(v11);
        }
    }
}

// layer 2: D+bias -> out remapped. grid (6144/96=64, 16, 2) = 2048 CTAs
__global__ __launch_bounds__(256, 2) void tgemm_l2(
        const __half* A0, const __half* B0, const float* b0,
        const __half* A1, const __half* B1, const float* b1,
        float* __restrict__ outf) {
    extern __shared__ __align__(16) char smem_raw[];
    const uint32_t base = smem_u32(smem_raw);
    float* s_bias = (float*)(smem_raw + NSTAGE * G_STAGE);
    int z = blockIdx.z, t = threadIdx.x;
    const __half* A = z ? A1 : A0;
    const __half* B = z ? B1 : B0;
    const float* bias = z ? b1 : b0;
    int m0 = blockIdx.y * 128, n0 = blockIdx.x * 96;
    if (t < 96) s_bias[t] = bias[n0 + t];

    const int lid = t & 31;
    const int mwarp = (t >> 5) & 1, nwarp = t >> 6;

    float acc[4][3][4];
    #pragma unroll
    for (int mi = 0; mi < 4; mi++)
        #pragma unroll
        for (int ni = 0; ni < 3; ni++)
            #pragma unroll
            for (int r = 0; r < 4; r++) acc[mi][ni][r] = 0.f;

    gemm_body96(A, B, QHD, VQn*QHD, m0, n0, base, t, acc);

    const int mb = m0 + mwarp * 64;
    const int nb = n0 + nwarp * 24;
    const int boff = z ? (NBQ * VQn) : 0;
    #pragma unroll
    for (int mi = 0; mi < 4; mi++) {
        int r0 = mb + mi*16 + (lid >> 2);
        #pragma unroll
        for (int ni = 0; ni < 3; ni++) {
            int n = nb + ni*8 + (lid & 3)*2;
            float v00 = acc[mi][ni][0] + s_bias[n   - n0];
            float v01 = acc[mi][ni][1] + s_bias[n+1 - n0];
            float v10 = acc[mi][ni][2] + s_bias[n   - n0];
            float v11 = acc[mi][ni][3] + s_bias[n+1 - n0];
            int vq = n / QHD, h = n - vq * QHD;
            int b0i = r0 >> 6, q0 = r0 & 63;
            int r1 = r0 + 8;
            int b1i = r1 >> 6, q1 = r1 & 63;
            size_t o0 = ((size_t)(b0i*OUTROWS + boff + q0*VQn + vq)) * QHD + h;
            size_t o1 = ((size_t)(b1i*OUTROWS + boff + q1*VQn + vq)) * QHD + h;
            outf[o0]   = v00; outf[o0+1] = v01;
            outf[o1]   = v10; outf[o1+1] = v11;
        }
    }
}

// ================= host =================
extern "C" void kernel_launch(void* const* d_in, const int* in_sizes, int n_in,
                              void* d_out, int out_size) {
    const float* sem     = (const float*)d_in[0];
    const float* propf   = (const float*)d_in[1];
    const float* boxc    = (const float*)d_in[2];
    const float* encxyz  = (const float*)d_in[3];
    const float* encf    = (const float*)d_in[4];
    const float* pcmin   = (const float*)d_in[5];
    const float* pcmax   = (const float*)d_in[6];
    const float* boxq    = (const float*)d_in[7];
    const float* boxqm   = (const float*)d_in[8];
    const float* clickq  = (const float*)d_in[9];
    const float* clickqm = (const float*)d_in[10];
    const float* gauss   = (const float*)d_in[11];
    const float* bw1     = (const float*)d_in[12];
    const float* bb1     = (const float*)d_in[13];
    const float* bw2     = (const float*)d_in[14];
    const float* bb2     = (const float*)d_in[15];
    const float* cw1     = (const float*)d_in[16];
    const float* cb1     = (const float*)d_in[17];
    const float* cw2     = (const float*)d_in[18];
    const float* cb2     = (const float*)d_in[19];
    float* out = (float*)d_out;

    void *bxA, *ckA, *w1b, *w1c, *w2b, *w2c, *h1, *h2;
    cudaGetSymbolAddress(&bxA, g_bxA); cudaGetSymbolAddress(&ckA, g_ckA);
    cudaGetSymbolAddress(&w1b, g_w1b); cudaGetSymbolAddress(&w1c, g_w1c);
    cudaGetSymbolAddress(&w2b, g_w2b); cudaGetSymbolAddress(&w2c, g_w2c);
    cudaGetSymbolAddress(&h1,  g_h1);  cudaGetSymbolAddress(&h2,  g_h2);

    cudaFuncSetAttribute(tgemm_l1, cudaFuncAttributeMaxDynamicSharedMemorySize, SMEM_G);
    cudaFuncSetAttribute(tgemm_l2, cudaFuncAttributeMaxDynamicSharedMemorySize, SMEM_G);

    prep_match_nn<<<NB + NB*(NPTS/NN_PTS), 256>>>(sem, boxc, boxq, encxyz, clickq);
    prep_gather_build<<<256 + MROWS/2, 256>>>(propf, encf, clickq, pcmin, pcmax, gauss);
    conv_all<<<2560, 256>>>(bw1, cw1, bw2, cw2, boxqm, clickqm, out + FEAT_ELEMS);

    // layer 1: both branches (z=2), M=2048 (128/CTA), N=768 (96/CTA) -> 256 CTAs
    tgemm_l1<<<dim3(QHD/96, MROWS/128, 2), 256, SMEM_G>>>(
        (__half*)bxA, (__half*)w1b, bb1, CDIM,   (__half*)h1,
        (__half*)ckA, (__half*)w1c, cb1, 2*CDIM, (__half*)h2);

    // layer 2: both branches (z=2), M=2048 (128/CTA), N=6144 (96/CTA) -> 2048 CTAs
    tgemm_l2<<<dim3((VQn*QHD)/96, MROWS/128, 2), 256, SMEM_G>>>(
        (__half*)h1, (__half*)w2b, bb2,
        (__half*)h2, (__half*)w2c, cb2, out);
}